// round 5
// baseline (speedup 1.0000x reference)
#include <cuda_runtime.h>
#include <math.h>

#define NT 256                 // threads per block
#define ILP 2                  // matrices per thread
#define MPB (NT * ILP)         // 512 matrices per block
#define FLOATS_PB (MPB * 9)    // 4608 floats
#define F4_PB (FLOATS_PB / 4)  // 1152 float4 per block
#define JITTER 1e-6f
#define NSWEEPS 3              // EXACT Givens: quadratic convergence

// FMA-pipe rsqrt, quake seed + N Newton steps.
// Seed err ~3.4e-2; 1 step ~1.75e-3; 2 steps ~4.6e-6.
// Avoids MUFU (rt_SMSP=8 would bottleneck at ~30M rsqrts).
template <int STEPS>
__device__ __forceinline__ float rsqrt_nr(float x) {
    x = fmaxf(x, 1e-30f);
    float y = __uint_as_float(0x5f3759dfu - (__float_as_uint(x) >> 1));
#pragma unroll
    for (int i = 0; i < STEPS; i++)
        y = y * fmaf(-0.5f * x, y * y, 1.5f);
    return y;
}

// EXACT annihilating Givens rotation on plane (p,q), division-free.
// 2-step Newton on both rsqrts is required: orthogonality error compounds
// linearly over rotations (1-step => ~4e-2 rel_err, measured in R2).
__device__ __forceinline__ void jrot(float& app, float& aqq, float& apq,
                                     float& apr, float& aqr,
                                     float vp[3], float vq[3]) {
    float d  = app - aqq;
    float r2 = fmaf(d, d, 4.0f * apq * apq);
    float w  = rsqrt_nr<2>(r2);
    float cos2t = fabsf(d) * w;
    float sin2t = 2.0f * apq * copysignf(w, d);
    float u     = fmaf(0.5f, cos2t, 0.5f);          // in [0.5, 1]
    float invc  = rsqrt_nr<2>(u);
    float c = u * invc;                              // sqrt(u)
    float s = 0.5f * sin2t * invc;
    bool tiny = (r2 < 1e-24f);
    c = tiny ? 1.0f : c;
    s = tiny ? 0.0f : s;

    float c2 = c * c, s2 = s * s, cs = c * s;
    float t_pp = fmaf(c2, app, fmaf(2.0f * cs, apq, s2 * aqq));
    float t_qq = (app + aqq) - t_pp;                 // trace preservation
    float t_pr = fmaf(c, apr, s * aqr);
    float t_qr = fmaf(c, aqr, -s * apr);
    app = t_pp; aqq = t_qq; apq = 0.0f; apr = t_pr; aqr = t_qr;
#pragma unroll
    for (int i = 0; i < 3; i++) {
        float a = vp[i], b = vq[i];
        vp[i] = fmaf(c, a, s * b);
        vq[i] = fmaf(c, b, -s * a);
    }
}

__device__ __forceinline__ void cross3(const float a[3], const float b[3], float o[3]) {
    o[0] = fmaf(a[1], b[2], -a[2] * b[1]);
    o[1] = fmaf(a[2], b[0], -a[0] * b[2]);
    o[2] = fmaf(a[0], b[1], -a[1] * b[0]);
}

__global__ void __launch_bounds__(NT)
orientation_bfn_kernel(const float* __restrict__ Rc,
                       const float* __restrict__ tarr,
                       const float* __restrict__ nz,
                       const float* __restrict__ ep,
                       float* __restrict__ out,
                       int Lmats) {
    __shared__ float4 s4[F4_PB];   // 18 KB: holds F through Jacobi phase
    float* sf = reinterpret_cast<float*>(s4);

    const int tid = threadIdx.x;
    const long long base = (long long)blockIdx.x * FLOATS_PB;  // float offset
    const int m0 = blockIdx.x * MPB;

    // All MPB=512 matrices in a block share one t (Lmats % 512 == 0 here).
    const float tval = tarr[m0 / Lmats];
    const float stval = sqrtf(tval);

    // Fused coalesced staging: F = t*R + sqrt(t)*noise + JITTER*eps, into SMEM.
    const float4* r4 = reinterpret_cast<const float4*>(Rc + base);
    const float4* n4 = reinterpret_cast<const float4*>(nz + base);
    const float4* e4 = reinterpret_cast<const float4*>(ep + base);
    for (int i = tid; i < F4_PB; i += NT) {
        float4 a = r4[i], b = n4[i], c = e4[i];
        float4 f;
        f.x = fmaf(tval, a.x, fmaf(stval, b.x, JITTER * c.x));
        f.y = fmaf(tval, a.y, fmaf(stval, b.y, JITTER * c.y));
        f.z = fmaf(tval, a.z, fmaf(stval, b.z, JITTER * c.z));
        f.w = fmaf(tval, a.w, fmaf(stval, b.w, JITTER * c.w));
        s4[i] = f;
    }
    __syncthreads();

    // Two independent matrices per thread: indices tid and tid+NT.
    // A = F^T F read straight out of SMEM (stride 9 -> conflict-free);
    // F itself stays in SMEM (re-read at epilogue) to keep regs low.
    float a00[ILP], a01[ILP], a02[ILP], a11[ILP], a12[ILP], a22[ILP];
    float V0[ILP][3], V1[ILP][3], V2[ILP][3];

#pragma unroll
    for (int j = 0; j < ILP; j++) {
        const float* Fp = sf + (tid + j * NT) * 9;
        float F0 = Fp[0], F1 = Fp[1], F2 = Fp[2];
        float F3 = Fp[3], F4v = Fp[4], F5 = Fp[5];
        float F6 = Fp[6], F7 = Fp[7], F8 = Fp[8];
        a00[j] = F0*F0 + F3*F3 + F6*F6;
        a01[j] = F0*F1 + F3*F4v + F6*F7;
        a02[j] = F0*F2 + F3*F5 + F6*F8;
        a11[j] = F1*F1 + F4v*F4v + F7*F7;
        a12[j] = F1*F2 + F4v*F5 + F7*F8;
        a22[j] = F2*F2 + F5*F5 + F8*F8;
        V0[j][0] = 1.f; V0[j][1] = 0.f; V0[j][2] = 0.f;
        V1[j][0] = 0.f; V1[j][1] = 1.f; V1[j][2] = 0.f;
        V2[j][0] = 0.f; V2[j][1] = 0.f; V2[j][2] = 1.f;
    }

    // Cyclic Jacobi, two interleaved independent chains (hides rsqrt latency).
#pragma unroll
    for (int sw = 0; sw < NSWEEPS; sw++) {
#pragma unroll
        for (int j = 0; j < ILP; j++)
            jrot(a00[j], a11[j], a01[j], a02[j], a12[j], V0[j], V1[j]);
#pragma unroll
        for (int j = 0; j < ILP; j++)
            jrot(a00[j], a22[j], a02[j], a01[j], a12[j], V0[j], V2[j]);
#pragma unroll
        for (int j = 0; j < ILP; j++)
            jrot(a11[j], a22[j], a12[j], a01[j], a02[j], V1[j], V2[j]);
    }

    // Per-matrix epilogue: sort, right-handed V, U via Gram-Schmidt, R = U V^T.
    float Rres[ILP][9];
#pragma unroll
    for (int j = 0; j < ILP; j++) {
        if (a00[j] < a11[j]) {
            float d = a00[j]; a00[j] = a11[j]; a11[j] = d;
#pragma unroll
            for (int i = 0; i < 3; i++) { float x = V0[j][i]; V0[j][i] = V1[j][i]; V1[j][i] = x; }
        }
        if (a00[j] < a22[j]) {
            float d = a00[j]; a00[j] = a22[j]; a22[j] = d;
#pragma unroll
            for (int i = 0; i < 3; i++) { float x = V0[j][i]; V0[j][i] = V2[j][i]; V2[j][i] = x; }
        }
        if (a11[j] < a22[j]) {
            float d = a11[j]; a11[j] = a22[j]; a22[j] = d;
#pragma unroll
            for (int i = 0; i < 3; i++) { float x = V1[j][i]; V1[j][i] = V2[j][i]; V2[j][i] = x; }
        }

        cross3(V0[j], V1[j], V2[j]);   // det(V) = +1

        // Re-read F from SMEM for b_i = F v_i.
        const float* Fp = sf + (tid + j * NT) * 9;
        float b1[3], b2[3];
#pragma unroll
        for (int i = 0; i < 3; i++) {
            float fa = Fp[3*i + 0], fb = Fp[3*i + 1], fc = Fp[3*i + 2];
            b1[i] = fmaf(fa, V0[j][0], fmaf(fb, V0[j][1], fc * V0[j][2]));
            b2[i] = fmaf(fa, V1[j][0], fmaf(fb, V1[j][1], fc * V1[j][2]));
        }

        float u1[3], u2[3], u3[3];
        float inv1 = rsqrt_nr<2>(b1[0]*b1[0] + b1[1]*b1[1] + b1[2]*b1[2]);
#pragma unroll
        for (int i = 0; i < 3; i++) u1[i] = b1[i] * inv1;

        float proj = fmaf(u1[0], b2[0], fmaf(u1[1], b2[1], u1[2] * b2[2]));
#pragma unroll
        for (int i = 0; i < 3; i++) b2[i] = fmaf(-proj, u1[i], b2[i]);
        float inv2 = rsqrt_nr<2>(b2[0]*b2[0] + b2[1]*b2[1] + b2[2]*b2[2]);
#pragma unroll
        for (int i = 0; i < 3; i++) u2[i] = b2[i] * inv2;

        cross3(u1, u2, u3);  // det(U) = +1; smallest-sigma sign flip implicit

#pragma unroll
        for (int i = 0; i < 3; i++)
#pragma unroll
            for (int k = 0; k < 3; k++)
                Rres[j][3*i + k] =
                    fmaf(u1[i], V0[j][k], fmaf(u2[i], V1[j][k], u3[i] * V2[j][k]));
    }

    __syncthreads();   // all F reads done before overwriting SMEM with R

#pragma unroll
    for (int j = 0; j < ILP; j++) {
        float* Rp = sf + (tid + j * NT) * 9;
#pragma unroll
        for (int k = 0; k < 9; k++) Rp[k] = Rres[j][k];
    }
    __syncthreads();

    // Coalesced float4 store of results.
    float4* o4 = reinterpret_cast<float4*>(out + base);
    for (int i = tid; i < F4_PB; i += NT) o4[i] = s4[i];
}

extern "C" void kernel_launch(void* const* d_in, const int* in_sizes, int n_in,
                              void* d_out, int out_size) {
    const float* Rc = (const float*)d_in[0];   // R_clean  (N*L*9)
    const float* t  = (const float*)d_in[1];   // t        (N)
    const float* nz = (const float*)d_in[2];   // noise    (N*L*9)
    const float* ep = (const float*)d_in[3];   // eps_noise(N*L*9)
    float* out = (float*)d_out;

    const int total = in_sizes[0];
    const int mats = total / 9;
    const int N = in_sizes[1];
    const int Lmats = mats / N;
    const int blocks = mats / MPB;  // 4096 for N=256, L=8192

    orientation_bfn_kernel<<<blocks, NT>>>(Rc, t, nz, ep, out, Lmats);
}

// round 6
// speedup vs baseline: 1.1039x; 1.1039x over previous
#include <cuda_runtime.h>
#include <math.h>

#define NT 256                 // threads per block, 1 matrix per thread
#define MPB NT                 // matrices per block
#define FLOATS_PB (MPB * 9)    // 2304 floats
#define F4_PB (FLOATS_PB / 4)  // 576 float4 per block
#define JITTER 1e-6f
#define NSWEEPS 3              // EXACT Givens: quadratic convergence

// FMA-pipe rsqrt, quake seed + N Newton steps.
// Seed err ~3.4e-2; 1 step ~1.75e-3; 2 steps ~4.6e-6.
// Avoids MUFU (rt_SMSP=8: 40M rsqrts would cost ~280us chip-wide).
template <int STEPS>
__device__ __forceinline__ float rsqrt_nr(float x) {
    x = fmaxf(x, 1e-30f);
    float y = __uint_as_float(0x5f3759dfu - (__float_as_uint(x) >> 1));
#pragma unroll
    for (int i = 0; i < STEPS; i++)
        y = y * fmaf(-0.5f * x, y * y, 1.5f);
    return y;
}

// EXACT annihilating Givens rotation on plane (p,q), division-free.
// 2-step Newton on both rsqrts is required: orthogonality error compounds
// linearly over rotations (1-step => ~4e-2 rel_err, measured in R2).
// Diagonal update via double-angle identities (cheaper, still exact):
//   a'pp = (app+aqq)/2 + (d/2) cos2t + apq sin2t,  a'qq by trace, a'pq = 0.
__device__ __forceinline__ void jrot(float& app, float& aqq, float& apq,
                                     float& apr, float& aqr,
                                     float vp[3], float vq[3]) {
    float d  = app - aqq;
    float r2 = fmaf(d, d, 4.0f * apq * apq);
    float w  = rsqrt_nr<2>(r2);
    float cos2t = fabsf(d) * w;
    float sin2t = 2.0f * apq * copysignf(w, d);
    float u     = fmaf(0.5f, cos2t, 0.5f);          // in [0.5, 1]
    float invc  = rsqrt_nr<2>(u);
    float c = u * invc;                              // sqrt(u)
    float s = 0.5f * sin2t * invc;
    bool tiny = (r2 < 1e-24f);
    c = tiny ? 1.0f : c;
    s = tiny ? 0.0f : s;
    cos2t = tiny ? 1.0f : cos2t;
    sin2t = tiny ? 0.0f : sin2t;

    float half_sum = 0.5f * (app + aqq);
    float t_pp = fmaf(0.5f * d, cos2t, fmaf(apq, sin2t, half_sum));
    float t_qq = 2.0f * half_sum - t_pp;             // trace preservation
    float t_pr = fmaf(c, apr, s * aqr);
    float t_qr = fmaf(c, aqr, -s * apr);
    app = t_pp; aqq = t_qq; apq = 0.0f; apr = t_pr; aqr = t_qr;
#pragma unroll
    for (int i = 0; i < 3; i++) {
        float a = vp[i], b = vq[i];
        vp[i] = fmaf(c, a, s * b);
        vq[i] = fmaf(c, b, -s * a);
    }
}

__device__ __forceinline__ void cross3(const float a[3], const float b[3], float o[3]) {
    o[0] = fmaf(a[1], b[2], -a[2] * b[1]);
    o[1] = fmaf(a[2], b[0], -a[0] * b[2]);
    o[2] = fmaf(a[0], b[1], -a[1] * b[0]);
}

__global__ void __launch_bounds__(NT, 8)   // force ~32 regs -> 64 warps/SM
orientation_bfn_kernel(const float* __restrict__ Rc,
                       const float* __restrict__ tarr,
                       const float* __restrict__ nz,
                       const float* __restrict__ ep,
                       float* __restrict__ out,
                       int Lmats) {
    __shared__ float4 s4[F4_PB];
    float* sf = reinterpret_cast<float*>(s4);

    const int tid = threadIdx.x;
    const long long base = (long long)blockIdx.x * FLOATS_PB;  // float offset
    const int m0 = blockIdx.x * MPB;

    // All MPB=256 matrices in a block share one t (Lmats % 256 == 0 here).
    const float tval = tarr[m0 / Lmats];
    const float stval = sqrtf(tval);

    // Fused coalesced staging: F = t*R + sqrt(t)*noise + JITTER*eps, into SMEM.
    const float4* r4 = reinterpret_cast<const float4*>(Rc + base);
    const float4* n4 = reinterpret_cast<const float4*>(nz + base);
    const float4* e4 = reinterpret_cast<const float4*>(ep + base);
#pragma unroll
    for (int i = tid; i < F4_PB; i += NT) {
        float4 a = r4[i], b = n4[i], c = e4[i];
        float4 f;
        f.x = fmaf(tval, a.x, fmaf(stval, b.x, JITTER * c.x));
        f.y = fmaf(tval, a.y, fmaf(stval, b.y, JITTER * c.y));
        f.z = fmaf(tval, a.z, fmaf(stval, b.z, JITTER * c.z));
        f.w = fmaf(tval, a.w, fmaf(stval, b.w, JITTER * c.w));
        s4[i] = f;
    }
    __syncthreads();

    // A = F^T F straight out of SMEM (stride 9 -> conflict-free). F stays in
    // SMEM through the Jacobi phase (re-read at epilogue) to keep regs <= 32.
    const float* Fp = sf + tid * 9;
    float a00, a01, a02, a11, a12, a22;
    {
        float F0 = Fp[0], F1 = Fp[1], F2 = Fp[2];
        float F3 = Fp[3], F4v = Fp[4], F5 = Fp[5];
        float F6 = Fp[6], F7 = Fp[7], F8 = Fp[8];
        a00 = F0*F0 + F3*F3 + F6*F6;
        a01 = F0*F1 + F3*F4v + F6*F7;
        a02 = F0*F2 + F3*F5 + F6*F8;
        a11 = F1*F1 + F4v*F4v + F7*F7;
        a12 = F1*F2 + F4v*F5 + F7*F8;
        a22 = F2*F2 + F5*F5 + F8*F8;
    }

    float V0[3] = {1.f, 0.f, 0.f};
    float V1[3] = {0.f, 1.f, 0.f};
    float V2[3] = {0.f, 0.f, 1.f};

#pragma unroll
    for (int sw = 0; sw < NSWEEPS; sw++) {
        jrot(a00, a11, a01, a02, a12, V0, V1);  // plane (0,1)
        jrot(a00, a22, a02, a01, a12, V0, V2);  // plane (0,2)
        jrot(a11, a22, a12, a01, a02, V1, V2);  // plane (1,2)
    }

    // Sort eigenpairs descending (3 compare-swaps).
    if (a00 < a11) {
        float d = a00; a00 = a11; a11 = d;
#pragma unroll
        for (int i = 0; i < 3; i++) { float x = V0[i]; V0[i] = V1[i]; V1[i] = x; }
    }
    if (a00 < a22) {
        float d = a00; a00 = a22; a22 = d;
#pragma unroll
        for (int i = 0; i < 3; i++) { float x = V0[i]; V0[i] = V2[i]; V2[i] = x; }
    }
    if (a11 < a22) {
        float d = a11; a11 = a22; a22 = d;
#pragma unroll
        for (int i = 0; i < 3; i++) { float x = V1[i]; V1[i] = V2[i]; V2[i] = x; }
    }

    // Force right-handed V: v3 = v1 x v2  => det(V) = +1.
    cross3(V0, V1, V2);

    // b_i = F v_i, F re-read from SMEM (keeps register count down).
    float b1[3], b2[3];
#pragma unroll
    for (int i = 0; i < 3; i++) {
        float fa = Fp[3*i + 0], fb = Fp[3*i + 1], fc = Fp[3*i + 2];
        b1[i] = fmaf(fa, V0[0], fmaf(fb, V0[1], fc * V0[2]));
        b2[i] = fmaf(fa, V1[0], fmaf(fb, V1[1], fc * V1[2]));
    }

    float u1[3], u2[3], u3[3];
    float inv1 = rsqrt_nr<2>(b1[0]*b1[0] + b1[1]*b1[1] + b1[2]*b1[2]);
#pragma unroll
    for (int i = 0; i < 3; i++) u1[i] = b1[i] * inv1;

    float proj = fmaf(u1[0], b2[0], fmaf(u1[1], b2[1], u1[2] * b2[2]));
#pragma unroll
    for (int i = 0; i < 3; i++) b2[i] = fmaf(-proj, u1[i], b2[i]);
    float inv2 = rsqrt_nr<2>(b2[0]*b2[0] + b2[1]*b2[1] + b2[2]*b2[2]);
#pragma unroll
    for (int i = 0; i < 3; i++) u2[i] = b2[i] * inv2;

    cross3(u1, u2, u3);  // det(U) = +1; smallest-sigma sign flip implicit

    __syncthreads();     // all F reads done before overwriting SMEM with R

    // R = U V^T  (matches reference incl. det correction)
    float* Rp = sf + tid * 9;
#pragma unroll
    for (int i = 0; i < 3; i++)
#pragma unroll
        for (int j = 0; j < 3; j++)
            Rp[3*i + j] = fmaf(u1[i], V0[j], fmaf(u2[i], V1[j], u3[i] * V2[j]));
    __syncthreads();

    // Coalesced float4 store of results.
    float4* o4 = reinterpret_cast<float4*>(out + base);
#pragma unroll
    for (int i = tid; i < F4_PB; i += NT) o4[i] = s4[i];
}

extern "C" void kernel_launch(void* const* d_in, const int* in_sizes, int n_in,
                              void* d_out, int out_size) {
    const float* Rc = (const float*)d_in[0];   // R_clean  (N*L*9)
    const float* t  = (const float*)d_in[1];   // t        (N)
    const float* nz = (const float*)d_in[2];   // noise    (N*L*9)
    const float* ep = (const float*)d_in[3];   // eps_noise(N*L*9)
    float* out = (float*)d_out;

    const int total = in_sizes[0];
    const int mats = total / 9;
    const int N = in_sizes[1];
    const int Lmats = mats / N;
    const int blocks = mats / MPB;  // 8192 for N=256, L=8192

    orientation_bfn_kernel<<<blocks, NT>>>(Rc, t, nz, ep, out, Lmats);
}

// round 7
// speedup vs baseline: 1.1684x; 1.0584x over previous
#include <cuda_runtime.h>
#include <math.h>
#include <stdint.h>

#define NT 128                  // threads per block
#define MPB 128                 // matrices per tile (1 per thread)
#define TILE_FLOATS (MPB * 9)   // 1152 floats per stream per tile
#define TILE_F4 (TILE_FLOATS/4) // 288 float4
#define GRID_BLOCKS 1216        // ~8 blocks/SM persistent
#define JITTER 1e-6f
#define NSWEEPS 3               // EXACT Givens: quadratic convergence

// ---------------- cp.async helpers ----------------
__device__ __forceinline__ uint32_t smem_u32(const void* p) {
    uint32_t a;
    asm("{ .reg .u64 t; cvta.to.shared.u64 t, %1; cvt.u32.u64 %0, t; }"
        : "=r"(a) : "l"(p));
    return a;
}
__device__ __forceinline__ void cp16(uint32_t dst, const void* src) {
    asm volatile("cp.async.cg.shared.global [%0], [%1], 16;"
                 :: "r"(dst), "l"(src));
}
__device__ __forceinline__ void cp_commit() {
    asm volatile("cp.async.commit_group;");
}
template <int N>
__device__ __forceinline__ void cp_wait() {
    asm volatile("cp.async.wait_group %0;" :: "n"(N));
}

// ---------------- math (identical to R6: proven rel_err 4.4e-5) ----------------
// FMA-pipe rsqrt, quake seed + 2 Newton steps (~4.6e-6). Avoids MUFU.
template <int STEPS>
__device__ __forceinline__ float rsqrt_nr(float x) {
    x = fmaxf(x, 1e-30f);
    float y = __uint_as_float(0x5f3759dfu - (__float_as_uint(x) >> 1));
#pragma unroll
    for (int i = 0; i < STEPS; i++)
        y = y * fmaf(-0.5f * x, y * y, 1.5f);
    return y;
}

// EXACT annihilating Givens rotation on plane (p,q), division-free.
__device__ __forceinline__ void jrot(float& app, float& aqq, float& apq,
                                     float& apr, float& aqr,
                                     float vp[3], float vq[3]) {
    float d  = app - aqq;
    float r2 = fmaf(d, d, 4.0f * apq * apq);
    float w  = rsqrt_nr<2>(r2);
    float cos2t = fabsf(d) * w;
    float sin2t = 2.0f * apq * copysignf(w, d);
    float u     = fmaf(0.5f, cos2t, 0.5f);          // in [0.5, 1]
    float invc  = rsqrt_nr<2>(u);
    float c = u * invc;                              // sqrt(u)
    float s = 0.5f * sin2t * invc;
    bool tiny = (r2 < 1e-24f);
    c = tiny ? 1.0f : c;
    s = tiny ? 0.0f : s;
    cos2t = tiny ? 1.0f : cos2t;
    sin2t = tiny ? 0.0f : sin2t;

    float half_sum = 0.5f * (app + aqq);
    float t_pp = fmaf(0.5f * d, cos2t, fmaf(apq, sin2t, half_sum));
    float t_qq = 2.0f * half_sum - t_pp;             // trace preservation
    float t_pr = fmaf(c, apr, s * aqr);
    float t_qr = fmaf(c, aqr, -s * apr);
    app = t_pp; aqq = t_qq; apq = 0.0f; apr = t_pr; aqr = t_qr;
#pragma unroll
    for (int i = 0; i < 3; i++) {
        float a = vp[i], b = vq[i];
        vp[i] = fmaf(c, a, s * b);
        vq[i] = fmaf(c, b, -s * a);
    }
}

__device__ __forceinline__ void cross3(const float a[3], const float b[3], float o[3]) {
    o[0] = fmaf(a[1], b[2], -a[2] * b[1]);
    o[1] = fmaf(a[2], b[0], -a[0] * b[2]);
    o[2] = fmaf(a[0], b[1], -a[1] * b[0]);
}

// ---------------- kernel ----------------
__global__ void __launch_bounds__(NT)
orientation_bfn_kernel(const float* __restrict__ Rc,
                       const float* __restrict__ tarr,
                       const float* __restrict__ nz,
                       const float* __restrict__ ep,
                       float* __restrict__ out,
                       int Lmats, int ntiles) {
    // Double-buffered raw staging: [stage][stream][float4]. 27.6 KB static.
    __shared__ float4 sbuf[2][3][TILE_F4];

    const int tid = threadIdx.x;

    // Prologue: prefetch first tile into stage 0.
    int tile0 = blockIdx.x;
    if (tile0 < ntiles) {
        uint32_t sb = smem_u32(&sbuf[0][0][0]);
        const float4* r4 = reinterpret_cast<const float4*>(Rc) + (long long)tile0 * TILE_F4;
        const float4* n4 = reinterpret_cast<const float4*>(nz) + (long long)tile0 * TILE_F4;
        const float4* e4 = reinterpret_cast<const float4*>(ep) + (long long)tile0 * TILE_F4;
        for (int i = tid; i < TILE_F4; i += NT) {
            cp16(sb + (0 * TILE_F4 + i) * 16, r4 + i);
            cp16(sb + (1 * TILE_F4 + i) * 16, n4 + i);
            cp16(sb + (2 * TILE_F4 + i) * 16, e4 + i);
        }
    }
    cp_commit();

    int j = 0;
    for (int tile = tile0; tile < ntiles; tile += GRID_BLOCKS, j++) {
        const int cur = j & 1;
        const int nxt_tile = tile + GRID_BLOCKS;

        // Issue prefetch for the next tile into the other stage, then drain
        // the current tile's group.
        if (nxt_tile < ntiles) {
            uint32_t sb = smem_u32(&sbuf[1 - cur][0][0]);
            const float4* r4 = reinterpret_cast<const float4*>(Rc) + (long long)nxt_tile * TILE_F4;
            const float4* n4 = reinterpret_cast<const float4*>(nz) + (long long)nxt_tile * TILE_F4;
            const float4* e4 = reinterpret_cast<const float4*>(ep) + (long long)nxt_tile * TILE_F4;
            for (int i = tid; i < TILE_F4; i += NT) {
                cp16(sb + (0 * TILE_F4 + i) * 16, r4 + i);
                cp16(sb + (1 * TILE_F4 + i) * 16, n4 + i);
                cp16(sb + (2 * TILE_F4 + i) * 16, e4 + i);
            }
            cp_commit();
            cp_wait<1>();   // current tile's group complete; next stays in flight
        } else {
            cp_wait<0>();
        }
        __syncthreads();    // raw data of 'cur' visible to all threads

        // All matrices in a 128-tile share one t (Lmats % 128 == 0).
        const float tval = __ldg(&tarr[(tile * MPB) / Lmats]);
        const float stv  = sqrtf(tval);

        // Fuse F = t*R + sqrt(t)*noise + JITTER*eps from own SMEM slots
        // (stride 9 across banks -> conflict-free). F lives in registers.
        const float* rr = reinterpret_cast<const float*>(&sbuf[cur][0][0]) + tid * 9;
        const float* rn = reinterpret_cast<const float*>(&sbuf[cur][1][0]) + tid * 9;
        const float* re = reinterpret_cast<const float*>(&sbuf[cur][2][0]) + tid * 9;
        float F[9];
#pragma unroll
        for (int k = 0; k < 9; k++)
            F[k] = fmaf(tval, rr[k], fmaf(stv, rn[k], JITTER * re[k]));

        // A = F^T F
        float a00 = F[0]*F[0] + F[3]*F[3] + F[6]*F[6];
        float a01 = F[0]*F[1] + F[3]*F[4] + F[6]*F[7];
        float a02 = F[0]*F[2] + F[3]*F[5] + F[6]*F[8];
        float a11 = F[1]*F[1] + F[4]*F[4] + F[7]*F[7];
        float a12 = F[1]*F[2] + F[4]*F[5] + F[7]*F[8];
        float a22 = F[2]*F[2] + F[5]*F[5] + F[8]*F[8];

        float V0[3] = {1.f, 0.f, 0.f};
        float V1[3] = {0.f, 1.f, 0.f};
        float V2[3] = {0.f, 0.f, 1.f};

#pragma unroll
        for (int sw = 0; sw < NSWEEPS; sw++) {
            jrot(a00, a11, a01, a02, a12, V0, V1);
            jrot(a00, a22, a02, a01, a12, V0, V2);
            jrot(a11, a22, a12, a01, a02, V1, V2);
        }

        // Sort eigenpairs descending.
        if (a00 < a11) {
            float d = a00; a00 = a11; a11 = d;
#pragma unroll
            for (int i = 0; i < 3; i++) { float x = V0[i]; V0[i] = V1[i]; V1[i] = x; }
        }
        if (a00 < a22) {
            float d = a00; a00 = a22; a22 = d;
#pragma unroll
            for (int i = 0; i < 3; i++) { float x = V0[i]; V0[i] = V2[i]; V2[i] = x; }
        }
        if (a11 < a22) {
            float d = a11; a11 = a22; a22 = d;
#pragma unroll
            for (int i = 0; i < 3; i++) { float x = V1[i]; V1[i] = V2[i]; V2[i] = x; }
        }

        cross3(V0, V1, V2);   // det(V) = +1

        // b_i = F v_i, Gram-Schmidt -> U, R = U V^T
        float b1[3], b2[3];
#pragma unroll
        for (int i = 0; i < 3; i++) {
            b1[i] = fmaf(F[3*i+0], V0[0], fmaf(F[3*i+1], V0[1], F[3*i+2] * V0[2]));
            b2[i] = fmaf(F[3*i+0], V1[0], fmaf(F[3*i+1], V1[1], F[3*i+2] * V1[2]));
        }
        float u1[3], u2[3], u3[3];
        float inv1 = rsqrt_nr<2>(b1[0]*b1[0] + b1[1]*b1[1] + b1[2]*b1[2]);
#pragma unroll
        for (int i = 0; i < 3; i++) u1[i] = b1[i] * inv1;
        float proj = fmaf(u1[0], b2[0], fmaf(u1[1], b2[1], u1[2] * b2[2]));
#pragma unroll
        for (int i = 0; i < 3; i++) b2[i] = fmaf(-proj, u1[i], b2[i]);
        float inv2 = rsqrt_nr<2>(b2[0]*b2[0] + b2[1]*b2[1] + b2[2]*b2[2]);
#pragma unroll
        for (int i = 0; i < 3; i++) u2[i] = b2[i] * inv2;
        cross3(u1, u2, u3);   // det(U) = +1; smallest-sigma flip implicit

        // Write R into this thread's OWN stream-0 slot (the slot it read F
        // from) -> no barrier needed between fuse-read and this write.
        float* Rp = reinterpret_cast<float*>(&sbuf[cur][0][0]) + tid * 9;
#pragma unroll
        for (int i = 0; i < 3; i++)
#pragma unroll
            for (int k = 0; k < 3; k++)
                Rp[3*i + k] = fmaf(u1[i], V0[k], fmaf(u2[i], V1[k], u3[i] * V2[k]));

        __syncthreads();      // all R written before cross-thread STG reads

        // Coalesced float4 store.
        float4* o4 = reinterpret_cast<float4*>(out) + (long long)tile * TILE_F4;
        for (int i = tid; i < TILE_F4; i += NT) o4[i] = sbuf[cur][0][i];

        __syncthreads();      // stage 'cur' free for next prefetch round
    }
}

extern "C" void kernel_launch(void* const* d_in, const int* in_sizes, int n_in,
                              void* d_out, int out_size) {
    const float* Rc = (const float*)d_in[0];   // R_clean  (N*L*9)
    const float* t  = (const float*)d_in[1];   // t        (N)
    const float* nz = (const float*)d_in[2];   // noise    (N*L*9)
    const float* ep = (const float*)d_in[3];   // eps_noise(N*L*9)
    float* out = (float*)d_out;

    const int total = in_sizes[0];
    const int mats = total / 9;
    const int N = in_sizes[1];
    const int Lmats = mats / N;
    const int ntiles = mats / MPB;             // 16384

    int blocks = ntiles < GRID_BLOCKS ? ntiles : GRID_BLOCKS;
    orientation_bfn_kernel<<<blocks, NT>>>(Rc, t, nz, ep, out, Lmats, ntiles);
}

// round 8
// speedup vs baseline: 1.1985x; 1.0257x over previous
#include <cuda_runtime.h>
#include <math.h>
#include <stdint.h>

#define NT 128                  // threads per block
#define MPB 128                 // matrices per tile (1 per thread)
#define TILE_FLOATS (MPB * 9)   // 1152 floats per stream per tile
#define TILE_F4 (TILE_FLOATS/4) // 288 float4
#define GRID_BLOCKS 1024        // 16384 tiles / 1024 = exactly 16 tiles/block
#define JITTER 1e-6f
#define NSWEEPS 3               // EXACT Givens: quadratic convergence

// ---------------- cp.async helpers ----------------
__device__ __forceinline__ uint32_t smem_u32(const void* p) {
    uint32_t a;
    asm("{ .reg .u64 t; cvta.to.shared.u64 t, %1; cvt.u32.u64 %0, t; }"
        : "=r"(a) : "l"(p));
    return a;
}
__device__ __forceinline__ void cp16(uint32_t dst, const void* src) {
    asm volatile("cp.async.cg.shared.global [%0], [%1], 16;"
                 :: "r"(dst), "l"(src));
}
__device__ __forceinline__ void cp_commit() {
    asm volatile("cp.async.commit_group;");
}
template <int N>
__device__ __forceinline__ void cp_wait() {
    asm volatile("cp.async.wait_group %0;" :: "n"(N));
}

// ---------------- math ----------------
// FMA-pipe rsqrt, quake seed + 2 Newton steps (~4.6e-6 rel err). Avoids MUFU.
// CLAMP=false skips the fmax when the argument is known >= 0.5.
template <bool CLAMP>
__device__ __forceinline__ float rsqrt_nr2(float x) {
    if (CLAMP) x = fmaxf(x, 1e-30f);
    float y = __uint_as_float(0x5f3759dfu - (__float_as_uint(x) >> 1));
    y = y * fmaf(-0.5f * x, y * y, 1.5f);
    y = y * fmaf(-0.5f * x, y * y, 1.5f);
    return y;
}

// EXACT annihilating Givens rotation on plane (p,q), division-free.
// 2-step Newton on both rsqrts is required: orthogonality error compounds
// linearly over rotations (1-step => ~4e-2 rel_err, measured in R2).
// Degenerate guard only on (c,s): unguarded degenerate case gives
// (c,s)=(0.707,0) which SCALES the V columns; cos2t/sin2t are bounded <=1
// so their degenerate garbage perturbs the diagonal by <= |d|+|apq| only.
__device__ __forceinline__ void jrot(float& app, float& aqq, float& apq,
                                     float& apr, float& aqr,
                                     float vp[3], float vq[3]) {
    float d  = app - aqq;
    float r2 = fmaf(d, d, 4.0f * apq * apq);
    float w  = rsqrt_nr2<true>(r2);
    float cos2t = fabsf(d) * w;                      // <= 1 always
    float sin2t = 2.0f * apq * copysignf(w, d);      // <= 1 always
    float u     = fmaf(0.5f, cos2t, 0.5f);           // in [0.5, 1]
    float invc  = rsqrt_nr2<false>(u);
    float c = u * invc;                              // sqrt(u)
    float s = 0.5f * sin2t * invc;
    bool tiny = (r2 < 1e-24f);
    c = tiny ? 1.0f : c;
    s = tiny ? 0.0f : s;

    float half_sum = 0.5f * (app + aqq);
    float t_pp = fmaf(0.5f * d, cos2t, fmaf(apq, sin2t, half_sum));
    float t_qq = fmaf(2.0f, half_sum, -t_pp);        // trace preservation
    float t_pr = fmaf(c, apr, s * aqr);
    float t_qr = fmaf(c, aqr, -s * apr);
    app = t_pp; aqq = t_qq; apq = 0.0f; apr = t_pr; aqr = t_qr;
#pragma unroll
    for (int i = 0; i < 3; i++) {
        float a = vp[i], b = vq[i];
        vp[i] = fmaf(c, a, s * b);
        vq[i] = fmaf(c, b, -s * a);
    }
}

__device__ __forceinline__ void cross3(const float a[3], const float b[3], float o[3]) {
    o[0] = fmaf(a[1], b[2], -a[2] * b[1]);
    o[1] = fmaf(a[2], b[0], -a[0] * b[2]);
    o[2] = fmaf(a[0], b[1], -a[1] * b[0]);
}

// ---------------- kernel ----------------
__global__ void __launch_bounds__(NT)
orientation_bfn_kernel(const float* __restrict__ Rc,
                       const float* __restrict__ tarr,
                       const float* __restrict__ nz,
                       const float* __restrict__ ep,
                       float* __restrict__ out,
                       int ntiles, int tshift, int tiles_per_t) {
    // Double-buffered raw staging: [stage][stream][float4]. 27.6 KB static.
    __shared__ float4 sbuf[2][3][TILE_F4];

    const int tid = threadIdx.x;

    // Prologue: prefetch first tile into stage 0.
    int tile0 = blockIdx.x;
    if (tile0 < ntiles) {
        uint32_t sb = smem_u32(&sbuf[0][0][0]);
        const float4* r4 = reinterpret_cast<const float4*>(Rc) + (long long)tile0 * TILE_F4;
        const float4* n4 = reinterpret_cast<const float4*>(nz) + (long long)tile0 * TILE_F4;
        const float4* e4 = reinterpret_cast<const float4*>(ep) + (long long)tile0 * TILE_F4;
#pragma unroll
        for (int i = tid; i < TILE_F4; i += NT) {
            cp16(sb + (0 * TILE_F4 + i) * 16, r4 + i);
            cp16(sb + (1 * TILE_F4 + i) * 16, n4 + i);
            cp16(sb + (2 * TILE_F4 + i) * 16, e4 + i);
        }
    }
    cp_commit();

    int j = 0;
    for (int tile = tile0; tile < ntiles; tile += GRID_BLOCKS, j++) {
        const int cur = j & 1;
        const int nxt_tile = tile + GRID_BLOCKS;

        // Issue prefetch for the next tile into the other stage, then drain
        // the current tile's group.
        if (nxt_tile < ntiles) {
            uint32_t sb = smem_u32(&sbuf[1 - cur][0][0]);
            const float4* r4 = reinterpret_cast<const float4*>(Rc) + (long long)nxt_tile * TILE_F4;
            const float4* n4 = reinterpret_cast<const float4*>(nz) + (long long)nxt_tile * TILE_F4;
            const float4* e4 = reinterpret_cast<const float4*>(ep) + (long long)nxt_tile * TILE_F4;
#pragma unroll
            for (int i = tid; i < TILE_F4; i += NT) {
                cp16(sb + (0 * TILE_F4 + i) * 16, r4 + i);
                cp16(sb + (1 * TILE_F4 + i) * 16, n4 + i);
                cp16(sb + (2 * TILE_F4 + i) * 16, e4 + i);
            }
            cp_commit();
            cp_wait<1>();   // current tile's group complete; next stays in flight
        } else {
            cp_wait<0>();
        }
        __syncthreads();    // raw data of 'cur' visible to all threads

        // t index: shift when tiles_per_t is a power of two (bench shape),
        // uniform-branch div fallback otherwise.
        const int t_idx = (tshift >= 0) ? (tile >> tshift) : (tile / tiles_per_t);
        const float tval = __ldg(&tarr[t_idx]);
        const float stv  = sqrtf(tval);

        // Fuse F = t*R + sqrt(t)*noise + JITTER*eps from own SMEM slots
        // (stride 9 across banks -> conflict-free). F lives in registers.
        const float* rr = reinterpret_cast<const float*>(&sbuf[cur][0][0]) + tid * 9;
        const float* rn = reinterpret_cast<const float*>(&sbuf[cur][1][0]) + tid * 9;
        const float* re = reinterpret_cast<const float*>(&sbuf[cur][2][0]) + tid * 9;
        float F[9];
#pragma unroll
        for (int k = 0; k < 9; k++)
            F[k] = fmaf(tval, rr[k], fmaf(stv, rn[k], JITTER * re[k]));

        // A = F^T F
        float a00 = F[0]*F[0] + F[3]*F[3] + F[6]*F[6];
        float a01 = F[0]*F[1] + F[3]*F[4] + F[6]*F[7];
        float a02 = F[0]*F[2] + F[3]*F[5] + F[6]*F[8];
        float a11 = F[1]*F[1] + F[4]*F[4] + F[7]*F[7];
        float a12 = F[1]*F[2] + F[4]*F[5] + F[7]*F[8];
        float a22 = F[2]*F[2] + F[5]*F[5] + F[8]*F[8];

        float V0[3] = {1.f, 0.f, 0.f};
        float V1[3] = {0.f, 1.f, 0.f};
        float V2[3] = {0.f, 0.f, 1.f};

#pragma unroll
        for (int sw = 0; sw < NSWEEPS; sw++) {
            jrot(a00, a11, a01, a02, a12, V0, V1);
            jrot(a00, a22, a02, a01, a12, V0, V2);
            jrot(a11, a22, a12, a01, a02, V1, V2);
        }

        // Pick eigenvectors of the largest and middle eigenvalues directly
        // (eigenvalues themselves are not needed afterwards; the third
        // direction is regenerated by cross product).
        bool gt01 = a00 >= a11;
        bool gt02 = a00 >= a22;
        bool gt12 = a11 >= a22;
        bool max0 = gt01 && gt02;
        bool max1 = (!gt01) && gt12;
        float vmax[3], vmid[3], v3[3];
#pragma unroll
        for (int i = 0; i < 3; i++) {
            float innerMax = gt12 ? V1[i] : V2[i];   // largest among {1,2}
            vmax[i] = max0 ? V0[i] : innerMax;
            float mid_if_max1 = gt02 ? V0[i] : V2[i];
            float mid_if_max2 = gt01 ? V0[i] : V1[i];
            vmid[i] = max0 ? innerMax : (max1 ? mid_if_max1 : mid_if_max2);
        }
        cross3(vmax, vmid, v3);   // right-handed third column, det(V)=+1

        // b_i = F v_i, Gram-Schmidt -> U, R = U V^T
        float b1[3], b2[3];
#pragma unroll
        for (int i = 0; i < 3; i++) {
            b1[i] = fmaf(F[3*i+0], vmax[0], fmaf(F[3*i+1], vmax[1], F[3*i+2] * vmax[2]));
            b2[i] = fmaf(F[3*i+0], vmid[0], fmaf(F[3*i+1], vmid[1], F[3*i+2] * vmid[2]));
        }
        float u1[3], u2[3], u3[3];
        float inv1 = rsqrt_nr2<true>(b1[0]*b1[0] + b1[1]*b1[1] + b1[2]*b1[2]);
#pragma unroll
        for (int i = 0; i < 3; i++) u1[i] = b1[i] * inv1;
        float proj = fmaf(u1[0], b2[0], fmaf(u1[1], b2[1], u1[2] * b2[2]));
#pragma unroll
        for (int i = 0; i < 3; i++) b2[i] = fmaf(-proj, u1[i], b2[i]);
        float inv2 = rsqrt_nr2<true>(b2[0]*b2[0] + b2[1]*b2[1] + b2[2]*b2[2]);
#pragma unroll
        for (int i = 0; i < 3; i++) u2[i] = b2[i] * inv2;
        cross3(u1, u2, u3);   // det(U)=+1; smallest-sigma flip implicit

        // Write R into this thread's OWN stream-0 slot (the slot it read F
        // from) -> no barrier needed between fuse-read and this write.
        float* Rp = reinterpret_cast<float*>(&sbuf[cur][0][0]) + tid * 9;
#pragma unroll
        for (int i = 0; i < 3; i++)
#pragma unroll
            for (int k = 0; k < 3; k++)
                Rp[3*i + k] = fmaf(u1[i], vmax[k], fmaf(u2[i], vmid[k], u3[i] * v3[k]));

        __syncthreads();      // all R written before cross-thread STG reads

        // Coalesced float4 store.
        float4* o4 = reinterpret_cast<float4*>(out) + (long long)tile * TILE_F4;
#pragma unroll
        for (int i = tid; i < TILE_F4; i += NT) o4[i] = sbuf[cur][0][i];

        __syncthreads();      // stage 'cur' free for next prefetch round
    }
}

extern "C" void kernel_launch(void* const* d_in, const int* in_sizes, int n_in,
                              void* d_out, int out_size) {
    const float* Rc = (const float*)d_in[0];   // R_clean  (N*L*9)
    const float* t  = (const float*)d_in[1];   // t        (N)
    const float* nz = (const float*)d_in[2];   // noise    (N*L*9)
    const float* ep = (const float*)d_in[3];   // eps_noise(N*L*9)
    float* out = (float*)d_out;

    const int total = in_sizes[0];
    const int mats = total / 9;
    const int N = in_sizes[1];
    const int Lmats = mats / N;
    const int ntiles = mats / MPB;             // 16384

    // tiles per t value; power-of-two -> shift on device (kills an int div)
    const int tiles_per_t = Lmats / MPB;       // 64 for the bench shape
    int tshift = -1;
    if (tiles_per_t > 0 && (tiles_per_t & (tiles_per_t - 1)) == 0) {
        tshift = 0;
        while ((1 << tshift) != tiles_per_t) tshift++;
    }

    int blocks = ntiles < GRID_BLOCKS ? ntiles : GRID_BLOCKS;
    orientation_bfn_kernel<<<blocks, NT>>>(Rc, t, nz, ep, out,
                                           ntiles, tshift, tiles_per_t);
}

// round 9
// speedup vs baseline: 1.2355x; 1.0309x over previous
#include <cuda_runtime.h>
#include <math.h>
#include <stdint.h>

#define NT 128                  // threads per block
#define MPB 128                 // matrices per tile (1 per thread)
#define TILE_FLOATS (MPB * 9)   // 1152 floats per stream per tile
#define TILE_F4 (TILE_FLOATS/4) // 288 float4
#define GRID_BLOCKS 1184        // 8 blocks/SM x 148 SMs: fills every SMEM slot
#define JITTER 1e-6f
#define NSWEEPS 3               // EXACT Givens: quadratic convergence

// ---------------- cp.async helpers ----------------
__device__ __forceinline__ uint32_t smem_u32(const void* p) {
    uint32_t a;
    asm("{ .reg .u64 t; cvta.to.shared.u64 t, %1; cvt.u32.u64 %0, t; }"
        : "=r"(a) : "l"(p));
    return a;
}
__device__ __forceinline__ void cp16(uint32_t dst, const void* src) {
    asm volatile("cp.async.cg.shared.global [%0], [%1], 16;"
                 :: "r"(dst), "l"(src));
}
__device__ __forceinline__ void cp_commit() {
    asm volatile("cp.async.commit_group;");
}
template <int N>
__device__ __forceinline__ void cp_wait() {
    asm volatile("cp.async.wait_group %0;" :: "n"(N));
}

// ---------------- math ----------------
// FMA-pipe rsqrt, quake seed + 2 Newton steps (~4.6e-6 rel err). Avoids MUFU.
// CLAMP=false skips the fmax when the argument is known >= 0.5.
template <bool CLAMP>
__device__ __forceinline__ float rsqrt_nr2(float x) {
    if (CLAMP) x = fmaxf(x, 1e-30f);
    float y = __uint_as_float(0x5f3759dfu - (__float_as_uint(x) >> 1));
    y = y * fmaf(-0.5f * x, y * y, 1.5f);
    y = y * fmaf(-0.5f * x, y * y, 1.5f);
    return y;
}

// EXACT annihilating Givens rotation on plane (p,q), division-free.
// 2-step Newton on both rsqrts is required: orthogonality error compounds
// linearly over rotations (1-step => ~4e-2 rel_err, measured in R2).
// OFFDIAG=false drops the apr/aqr updates (legal only for the final rotation,
// whose off-diagonal outputs feed nothing).
template <bool OFFDIAG>
__device__ __forceinline__ void jrot(float& app, float& aqq, float& apq,
                                     float& apr, float& aqr,
                                     float vp[3], float vq[3]) {
    float d  = app - aqq;
    float r2 = fmaf(d, d, 4.0f * apq * apq);
    float w  = rsqrt_nr2<true>(r2);
    float cos2t = fabsf(d) * w;                      // <= 1 always
    float sin2t = 2.0f * apq * copysignf(w, d);      // <= 1 always
    float u     = fmaf(0.5f, cos2t, 0.5f);           // in [0.5, 1]
    float invc  = rsqrt_nr2<false>(u);
    float c = u * invc;                              // sqrt(u)
    float s = 0.5f * sin2t * invc;
    bool tiny = (r2 < 1e-24f);
    c = tiny ? 1.0f : c;
    s = tiny ? 0.0f : s;

    float half_sum = 0.5f * (app + aqq);
    float t_pp = fmaf(0.5f * d, cos2t, fmaf(apq, sin2t, half_sum));
    float t_qq = fmaf(2.0f, half_sum, -t_pp);        // trace preservation
    app = t_pp; aqq = t_qq; apq = 0.0f;
    if (OFFDIAG) {
        float t_pr = fmaf(c, apr, s * aqr);
        float t_qr = fmaf(c, aqr, -s * apr);
        apr = t_pr; aqr = t_qr;
    }
#pragma unroll
    for (int i = 0; i < 3; i++) {
        float a = vp[i], b = vq[i];
        vp[i] = fmaf(c, a, s * b);
        vq[i] = fmaf(c, b, -s * a);
    }
}

__device__ __forceinline__ void cross3(const float a[3], const float b[3], float o[3]) {
    o[0] = fmaf(a[1], b[2], -a[2] * b[1]);
    o[1] = fmaf(a[2], b[0], -a[0] * b[2]);
    o[2] = fmaf(a[0], b[1], -a[1] * b[0]);
}

// ---------------- kernel ----------------
__global__ void __launch_bounds__(NT)
orientation_bfn_kernel(const float* __restrict__ Rc,
                       const float* __restrict__ tarr,
                       const float* __restrict__ nz,
                       const float* __restrict__ ep,
                       float* __restrict__ out,
                       int ntiles, int tshift, int tiles_per_t) {
    // Double-buffered raw staging: [stage][stream][float4]. 27.6 KB static.
    __shared__ float4 sbuf[2][3][TILE_F4];

    const int tid = threadIdx.x;

    // Prologue: prefetch first tile into stage 0.
    int tile0 = blockIdx.x;
    if (tile0 < ntiles) {
        uint32_t sb = smem_u32(&sbuf[0][0][0]);
        const float4* r4 = reinterpret_cast<const float4*>(Rc) + (long long)tile0 * TILE_F4;
        const float4* n4 = reinterpret_cast<const float4*>(nz) + (long long)tile0 * TILE_F4;
        const float4* e4 = reinterpret_cast<const float4*>(ep) + (long long)tile0 * TILE_F4;
#pragma unroll
        for (int i = tid; i < TILE_F4; i += NT) {
            cp16(sb + (0 * TILE_F4 + i) * 16, r4 + i);
            cp16(sb + (1 * TILE_F4 + i) * 16, n4 + i);
            cp16(sb + (2 * TILE_F4 + i) * 16, e4 + i);
        }
    }
    cp_commit();

    int j = 0;
    for (int tile = tile0; tile < ntiles; tile += GRID_BLOCKS, j++) {
        const int cur = j & 1;
        const int nxt_tile = tile + GRID_BLOCKS;

        // Issue prefetch for the next tile into the other stage, then drain
        // the current tile's group.
        if (nxt_tile < ntiles) {
            uint32_t sb = smem_u32(&sbuf[1 - cur][0][0]);
            const float4* r4 = reinterpret_cast<const float4*>(Rc) + (long long)nxt_tile * TILE_F4;
            const float4* n4 = reinterpret_cast<const float4*>(nz) + (long long)nxt_tile * TILE_F4;
            const float4* e4 = reinterpret_cast<const float4*>(ep) + (long long)nxt_tile * TILE_F4;
#pragma unroll
            for (int i = tid; i < TILE_F4; i += NT) {
                cp16(sb + (0 * TILE_F4 + i) * 16, r4 + i);
                cp16(sb + (1 * TILE_F4 + i) * 16, n4 + i);
                cp16(sb + (2 * TILE_F4 + i) * 16, e4 + i);
            }
            cp_commit();
            cp_wait<1>();   // current tile's group complete; next stays in flight
        } else {
            cp_wait<0>();
        }
        __syncthreads();    // raw data of 'cur' visible to all threads

        // t index: shift when tiles_per_t is a power of two (bench shape),
        // uniform-branch div fallback otherwise.
        const int t_idx = (tshift >= 0) ? (tile >> tshift) : (tile / tiles_per_t);
        const float tval = __ldg(&tarr[t_idx]);
        const float stv  = sqrtf(tval);

        // Fuse F = t*R + sqrt(t)*noise + JITTER*eps from own SMEM slots
        // (stride 9 across banks -> conflict-free). F lives in registers.
        const float* rr = reinterpret_cast<const float*>(&sbuf[cur][0][0]) + tid * 9;
        const float* rn = reinterpret_cast<const float*>(&sbuf[cur][1][0]) + tid * 9;
        const float* re = reinterpret_cast<const float*>(&sbuf[cur][2][0]) + tid * 9;
        float F[9];
#pragma unroll
        for (int k = 0; k < 9; k++)
            F[k] = fmaf(tval, rr[k], fmaf(stv, rn[k], JITTER * re[k]));

        // A = F^T F
        float a00 = F[0]*F[0] + F[3]*F[3] + F[6]*F[6];
        float a01 = F[0]*F[1] + F[3]*F[4] + F[6]*F[7];
        float a02 = F[0]*F[2] + F[3]*F[5] + F[6]*F[8];
        float a11 = F[1]*F[1] + F[4]*F[4] + F[7]*F[7];
        float a12 = F[1]*F[2] + F[4]*F[5] + F[7]*F[8];
        float a22 = F[2]*F[2] + F[5]*F[5] + F[8]*F[8];

        float V0[3] = {1.f, 0.f, 0.f};
        float V1[3] = {0.f, 1.f, 0.f};
        float V2[3] = {0.f, 0.f, 1.f};

        // 3 exact cyclic sweeps; final rotation skips dead off-diag updates.
        jrot<true >(a00, a11, a01, a02, a12, V0, V1);
        jrot<true >(a00, a22, a02, a01, a12, V0, V2);
        jrot<true >(a11, a22, a12, a01, a02, V1, V2);
        jrot<true >(a00, a11, a01, a02, a12, V0, V1);
        jrot<true >(a00, a22, a02, a01, a12, V0, V2);
        jrot<true >(a11, a22, a12, a01, a02, V1, V2);
        jrot<true >(a00, a11, a01, a02, a12, V0, V1);
        jrot<true >(a00, a22, a02, a01, a12, V0, V2);
        jrot<false>(a11, a22, a12, a01, a02, V1, V2);

        // Pick eigenvectors of the largest and middle eigenvalues directly.
        bool gt01 = a00 >= a11;
        bool gt02 = a00 >= a22;
        bool gt12 = a11 >= a22;
        bool max0 = gt01 && gt02;
        bool max1 = (!gt01) && gt12;
        float vmax[3], vmid[3], v3[3];
#pragma unroll
        for (int i = 0; i < 3; i++) {
            float innerMax = gt12 ? V1[i] : V2[i];   // largest among {1,2}
            vmax[i] = max0 ? V0[i] : innerMax;
            float mid_if_max1 = gt02 ? V0[i] : V2[i];
            float mid_if_max2 = gt01 ? V0[i] : V1[i];
            vmid[i] = max0 ? innerMax : (max1 ? mid_if_max1 : mid_if_max2);
        }
        cross3(vmax, vmid, v3);   // right-handed third column, det(V)=+1

        // b_i = F v_i, Gram-Schmidt -> U, R = U V^T
        float b1[3], b2[3];
#pragma unroll
        for (int i = 0; i < 3; i++) {
            b1[i] = fmaf(F[3*i+0], vmax[0], fmaf(F[3*i+1], vmax[1], F[3*i+2] * vmax[2]));
            b2[i] = fmaf(F[3*i+0], vmid[0], fmaf(F[3*i+1], vmid[1], F[3*i+2] * vmid[2]));
        }
        float u1[3], u2[3], u3[3];
        float inv1 = rsqrt_nr2<true>(b1[0]*b1[0] + b1[1]*b1[1] + b1[2]*b1[2]);
#pragma unroll
        for (int i = 0; i < 3; i++) u1[i] = b1[i] * inv1;
        float proj = fmaf(u1[0], b2[0], fmaf(u1[1], b2[1], u1[2] * b2[2]));
#pragma unroll
        for (int i = 0; i < 3; i++) b2[i] = fmaf(-proj, u1[i], b2[i]);
        float inv2 = rsqrt_nr2<true>(b2[0]*b2[0] + b2[1]*b2[1] + b2[2]*b2[2]);
#pragma unroll
        for (int i = 0; i < 3; i++) u2[i] = b2[i] * inv2;
        cross3(u1, u2, u3);   // det(U)=+1; smallest-sigma flip implicit

        // Write R into this thread's OWN stream-0 slot (the slot it read F
        // from) -> no barrier needed between fuse-read and this write.
        float* Rp = reinterpret_cast<float*>(&sbuf[cur][0][0]) + tid * 9;
#pragma unroll
        for (int i = 0; i < 3; i++)
#pragma unroll
            for (int k = 0; k < 3; k++)
                Rp[3*i + k] = fmaf(u1[i], vmax[k], fmaf(u2[i], vmid[k], u3[i] * v3[k]));

        __syncthreads();      // all R written before cross-thread STG reads

        // Coalesced float4 store.
        float4* o4 = reinterpret_cast<float4*>(out) + (long long)tile * TILE_F4;
#pragma unroll
        for (int i = tid; i < TILE_F4; i += NT) o4[i] = sbuf[cur][0][i];

        __syncthreads();      // stage 'cur' free for next prefetch round
    }
}

extern "C" void kernel_launch(void* const* d_in, const int* in_sizes, int n_in,
                              void* d_out, int out_size) {
    const float* Rc = (const float*)d_in[0];   // R_clean  (N*L*9)
    const float* t  = (const float*)d_in[1];   // t        (N)
    const float* nz = (const float*)d_in[2];   // noise    (N*L*9)
    const float* ep = (const float*)d_in[3];   // eps_noise(N*L*9)
    float* out = (float*)d_out;

    const int total = in_sizes[0];
    const int mats = total / 9;
    const int N = in_sizes[1];
    const int Lmats = mats / N;
    const int ntiles = mats / MPB;             // 16384

    // tiles per t value; power-of-two -> shift on device (kills an int div)
    const int tiles_per_t = Lmats / MPB;       // 64 for the bench shape
    int tshift = -1;
    if (tiles_per_t > 0 && (tiles_per_t & (tiles_per_t - 1)) == 0) {
        tshift = 0;
        while ((1 << tshift) != tiles_per_t) tshift++;
    }

    int blocks = ntiles < GRID_BLOCKS ? ntiles : GRID_BLOCKS;
    orientation_bfn_kernel<<<blocks, NT>>>(Rc, t, nz, ep, out,
                                           ntiles, tshift, tiles_per_t);
}

// round 10
// speedup vs baseline: 1.3778x; 1.1152x over previous
#include <cuda_runtime.h>
#include <math.h>
#include <stdint.h>

#define NT 128                  // threads per block
#define MPB 128                 // matrices per tile (1 per thread)
#define TILE_FLOATS (MPB * 9)   // 1152 floats per stream per tile
#define TILE_F4 (TILE_FLOATS/4) // 288 float4
#define GRID_BLOCKS 1184        // 8 blocks/SM x 148 SMs
#define JITTER 1e-6f

// ---------------- cp.async helpers ----------------
__device__ __forceinline__ uint32_t smem_u32(const void* p) {
    uint32_t a;
    asm("{ .reg .u64 t; cvta.to.shared.u64 t, %1; cvt.u32.u64 %0, t; }"
        : "=r"(a) : "l"(p));
    return a;
}
__device__ __forceinline__ void cp16(uint32_t dst, const void* src) {
    asm volatile("cp.async.cg.shared.global [%0], [%1], 16;"
                 :: "r"(dst), "l"(src));
}
__device__ __forceinline__ void cp_commit() {
    asm volatile("cp.async.commit_group;");
}
template <int N>
__device__ __forceinline__ void cp_wait() {
    asm volatile("cp.async.wait_group %0;" :: "n"(N));
}

// ---------------- math (unchanged: proven rel_err 4.4e-5) ----------------
// FMA-pipe rsqrt, quake seed + 2 Newton steps (~4.6e-6 rel err). Avoids MUFU.
template <bool CLAMP>
__device__ __forceinline__ float rsqrt_nr2(float x) {
    if (CLAMP) x = fmaxf(x, 1e-30f);
    float y = __uint_as_float(0x5f3759dfu - (__float_as_uint(x) >> 1));
    y = y * fmaf(-0.5f * x, y * y, 1.5f);
    y = y * fmaf(-0.5f * x, y * y, 1.5f);
    return y;
}

// EXACT annihilating Givens rotation on plane (p,q), division-free.
// 2-step Newton on both rsqrts required: orthogonality error compounds
// linearly over rotations (1-step => ~4e-2 rel_err, measured in R2).
template <bool OFFDIAG>
__device__ __forceinline__ void jrot(float& app, float& aqq, float& apq,
                                     float& apr, float& aqr,
                                     float vp[3], float vq[3]) {
    float d  = app - aqq;
    float r2 = fmaf(d, d, 4.0f * apq * apq);
    float w  = rsqrt_nr2<true>(r2);
    float cos2t = fabsf(d) * w;                      // <= 1 always
    float sin2t = 2.0f * apq * copysignf(w, d);      // <= 1 always
    float u     = fmaf(0.5f, cos2t, 0.5f);           // in [0.5, 1]
    float invc  = rsqrt_nr2<false>(u);
    float c = u * invc;                              // sqrt(u)
    float s = 0.5f * sin2t * invc;
    bool tiny = (r2 < 1e-24f);
    c = tiny ? 1.0f : c;
    s = tiny ? 0.0f : s;

    float half_sum = 0.5f * (app + aqq);
    float t_pp = fmaf(0.5f * d, cos2t, fmaf(apq, sin2t, half_sum));
    float t_qq = fmaf(2.0f, half_sum, -t_pp);        // trace preservation
    app = t_pp; aqq = t_qq; apq = 0.0f;
    if (OFFDIAG) {
        float t_pr = fmaf(c, apr, s * aqr);
        float t_qr = fmaf(c, aqr, -s * apr);
        apr = t_pr; aqr = t_qr;
    }
#pragma unroll
    for (int i = 0; i < 3; i++) {
        float a = vp[i], b = vq[i];
        vp[i] = fmaf(c, a, s * b);
        vq[i] = fmaf(c, b, -s * a);
    }
}

__device__ __forceinline__ void cross3(const float a[3], const float b[3], float o[3]) {
    o[0] = fmaf(a[1], b[2], -a[2] * b[1]);
    o[1] = fmaf(a[2], b[0], -a[0] * b[2]);
    o[2] = fmaf(a[0], b[1], -a[1] * b[0]);
}

// ---------------- kernel ----------------
__global__ void __launch_bounds__(NT, 8)
orientation_bfn_kernel(const float* __restrict__ Rc,
                       const float* __restrict__ tarr,
                       const float* __restrict__ nz,
                       const float* __restrict__ ep,
                       float* __restrict__ out,
                       int ntiles, int tshift, int tiles_per_t) {
    // SINGLE raw staging buffer (13.8 KB) + R staging (4.6 KB) = 18.4 KB.
    // The raw buffer is drained into registers at the top of each tile, so
    // the next tile's prefetch can reuse it immediately after -> double
    // buffering is unnecessary and 8 blocks/SM fit (R9 only got 6).
    __shared__ float4 raw[3][TILE_F4];
    __shared__ float4 rbuf[TILE_F4];

    const int tid = threadIdx.x;

    // Prologue: prefetch first tile.
    int tile0 = blockIdx.x;
    {
        uint32_t sb = smem_u32(&raw[0][0]);
        const float4* r4 = reinterpret_cast<const float4*>(Rc) + (long long)tile0 * TILE_F4;
        const float4* n4 = reinterpret_cast<const float4*>(nz) + (long long)tile0 * TILE_F4;
        const float4* e4 = reinterpret_cast<const float4*>(ep) + (long long)tile0 * TILE_F4;
#pragma unroll
        for (int i = tid; i < TILE_F4; i += NT) {
            cp16(sb + (0 * TILE_F4 + i) * 16, r4 + i);
            cp16(sb + (1 * TILE_F4 + i) * 16, n4 + i);
            cp16(sb + (2 * TILE_F4 + i) * 16, e4 + i);
        }
        cp_commit();
    }

    for (int tile = tile0; tile < ntiles; tile += GRID_BLOCKS) {
        cp_wait<0>();
        __syncthreads();    // raw tile visible to all threads

        // t index: shift when tiles_per_t is a power of two (bench shape).
        const int t_idx = (tshift >= 0) ? (tile >> tshift) : (tile / tiles_per_t);
        const float tval = __ldg(&tarr[t_idx]);
        const float stv  = sqrtf(tval);

        // Drain raw buffer: F = t*R + sqrt(t)*noise + JITTER*eps into regs
        // (stride 9 across banks -> conflict-free).
        const float* rr = reinterpret_cast<const float*>(&raw[0][0]) + tid * 9;
        const float* rn = reinterpret_cast<const float*>(&raw[1][0]) + tid * 9;
        const float* re = reinterpret_cast<const float*>(&raw[2][0]) + tid * 9;
        float F[9];
#pragma unroll
        for (int k = 0; k < 9; k++)
            F[k] = fmaf(tval, rr[k], fmaf(stv, rn[k], JITTER * re[k]));

        __syncthreads();    // all fuse reads done -> raw buffer reusable

        // Issue next tile's prefetch NOW; its latency hides under the
        // Jacobi compute below.
        const int nxt_tile = tile + GRID_BLOCKS;
        if (nxt_tile < ntiles) {
            uint32_t sb = smem_u32(&raw[0][0]);
            const float4* r4 = reinterpret_cast<const float4*>(Rc) + (long long)nxt_tile * TILE_F4;
            const float4* n4 = reinterpret_cast<const float4*>(nz) + (long long)nxt_tile * TILE_F4;
            const float4* e4 = reinterpret_cast<const float4*>(ep) + (long long)nxt_tile * TILE_F4;
#pragma unroll
            for (int i = tid; i < TILE_F4; i += NT) {
                cp16(sb + (0 * TILE_F4 + i) * 16, r4 + i);
                cp16(sb + (1 * TILE_F4 + i) * 16, n4 + i);
                cp16(sb + (2 * TILE_F4 + i) * 16, e4 + i);
            }
            cp_commit();
        }

        // A = F^T F
        float a00 = F[0]*F[0] + F[3]*F[3] + F[6]*F[6];
        float a01 = F[0]*F[1] + F[3]*F[4] + F[6]*F[7];
        float a02 = F[0]*F[2] + F[3]*F[5] + F[6]*F[8];
        float a11 = F[1]*F[1] + F[4]*F[4] + F[7]*F[7];
        float a12 = F[1]*F[2] + F[4]*F[5] + F[7]*F[8];
        float a22 = F[2]*F[2] + F[5]*F[5] + F[8]*F[8];

        float V0[3] = {1.f, 0.f, 0.f};
        float V1[3] = {0.f, 1.f, 0.f};
        float V2[3] = {0.f, 0.f, 1.f};

        // 3 exact cyclic sweeps; final rotation skips dead off-diag updates.
        jrot<true >(a00, a11, a01, a02, a12, V0, V1);
        jrot<true >(a00, a22, a02, a01, a12, V0, V2);
        jrot<true >(a11, a22, a12, a01, a02, V1, V2);
        jrot<true >(a00, a11, a01, a02, a12, V0, V1);
        jrot<true >(a00, a22, a02, a01, a12, V0, V2);
        jrot<true >(a11, a22, a12, a01, a02, V1, V2);
        jrot<true >(a00, a11, a01, a02, a12, V0, V1);
        jrot<true >(a00, a22, a02, a01, a12, V0, V2);
        jrot<false>(a11, a22, a12, a01, a02, V1, V2);

        // Pick eigenvectors of the largest and middle eigenvalues directly.
        bool gt01 = a00 >= a11;
        bool gt02 = a00 >= a22;
        bool gt12 = a11 >= a22;
        bool max0 = gt01 && gt02;
        bool max1 = (!gt01) && gt12;
        float vmax[3], vmid[3], v3[3];
#pragma unroll
        for (int i = 0; i < 3; i++) {
            float innerMax = gt12 ? V1[i] : V2[i];   // largest among {1,2}
            vmax[i] = max0 ? V0[i] : innerMax;
            float mid_if_max1 = gt02 ? V0[i] : V2[i];
            float mid_if_max2 = gt01 ? V0[i] : V1[i];
            vmid[i] = max0 ? innerMax : (max1 ? mid_if_max1 : mid_if_max2);
        }
        cross3(vmax, vmid, v3);   // right-handed third column, det(V)=+1

        // b_i = F v_i, Gram-Schmidt -> U, R = U V^T
        float b1[3], b2[3];
#pragma unroll
        for (int i = 0; i < 3; i++) {
            b1[i] = fmaf(F[3*i+0], vmax[0], fmaf(F[3*i+1], vmax[1], F[3*i+2] * vmax[2]));
            b2[i] = fmaf(F[3*i+0], vmid[0], fmaf(F[3*i+1], vmid[1], F[3*i+2] * vmid[2]));
        }
        float u1[3], u2[3], u3[3];
        float inv1 = rsqrt_nr2<true>(b1[0]*b1[0] + b1[1]*b1[1] + b1[2]*b1[2]);
#pragma unroll
        for (int i = 0; i < 3; i++) u1[i] = b1[i] * inv1;
        float proj = fmaf(u1[0], b2[0], fmaf(u1[1], b2[1], u1[2] * b2[2]));
#pragma unroll
        for (int i = 0; i < 3; i++) b2[i] = fmaf(-proj, u1[i], b2[i]);
        float inv2 = rsqrt_nr2<true>(b2[0]*b2[0] + b2[1]*b2[1] + b2[2]*b2[2]);
#pragma unroll
        for (int i = 0; i < 3; i++) u2[i] = b2[i] * inv2;
        cross3(u1, u2, u3);   // det(U)=+1; smallest-sigma flip implicit

        // R = U V^T into the R staging buffer (own slot, stride 9).
        float* Rp = reinterpret_cast<float*>(&rbuf[0]) + tid * 9;
#pragma unroll
        for (int i = 0; i < 3; i++)
#pragma unroll
            for (int k = 0; k < 3; k++)
                Rp[3*i + k] = fmaf(u1[i], vmax[k], fmaf(u2[i], vmid[k], u3[i] * v3[k]));

        __syncthreads();      // all R written before cross-thread STG reads

        // Coalesced float4 store. (The next iteration's top barrier orders
        // these rbuf reads before anyone rewrites rbuf.)
        float4* o4 = reinterpret_cast<float4*>(out) + (long long)tile * TILE_F4;
#pragma unroll
        for (int i = tid; i < TILE_F4; i += NT) o4[i] = rbuf[i];
    }
}

extern "C" void kernel_launch(void* const* d_in, const int* in_sizes, int n_in,
                              void* d_out, int out_size) {
    const float* Rc = (const float*)d_in[0];   // R_clean  (N*L*9)
    const float* t  = (const float*)d_in[1];   // t        (N)
    const float* nz = (const float*)d_in[2];   // noise    (N*L*9)
    const float* ep = (const float*)d_in[3];   // eps_noise(N*L*9)
    float* out = (float*)d_out;

    const int total = in_sizes[0];
    const int mats = total / 9;
    const int N = in_sizes[1];
    const int Lmats = mats / N;
    const int ntiles = mats / MPB;             // 16384

    // tiles per t value; power-of-two -> shift on device (kills an int div)
    const int tiles_per_t = Lmats / MPB;       // 64 for the bench shape
    int tshift = -1;
    if (tiles_per_t > 0 && (tiles_per_t & (tiles_per_t - 1)) == 0) {
        tshift = 0;
        while ((1 << tshift) != tiles_per_t) tshift++;
    }

    int blocks = ntiles < GRID_BLOCKS ? ntiles : GRID_BLOCKS;
    orientation_bfn_kernel<<<blocks, NT>>>(Rc, t, nz, ep, out,
                                           ntiles, tshift, tiles_per_t);
}

// round 12
// speedup vs baseline: 1.5041x; 1.0917x over previous
#include <cuda_runtime.h>
#include <math.h>
#include <stdint.h>

#define NT 128                  // threads per block
#define MPB 128                 // matrices per tile (1 per thread)
#define TILE_FLOATS (MPB * 9)   // 1152 floats per stream per tile
#define TILE_F4 (TILE_FLOATS/4) // 288 float4
#define GRID_BLOCKS 1184        // 8 blocks/SM x 148 SMs
#define JITTER 1e-6f

// ---------------- cp.async helpers ----------------
__device__ __forceinline__ uint32_t smem_u32(const void* p) {
    uint32_t a;
    asm("{ .reg .u64 t; cvta.to.shared.u64 t, %1; cvt.u32.u64 %0, t; }"
        : "=r"(a) : "l"(p));
    return a;
}
__device__ __forceinline__ void cp16(uint32_t dst, const void* src) {
    asm volatile("cp.async.cg.shared.global [%0], [%1], 16;"
                 :: "r"(dst), "l"(src));
}
__device__ __forceinline__ void cp_commit() {
    asm volatile("cp.async.commit_group;");
}
template <int N>
__device__ __forceinline__ void cp_wait() {
    asm volatile("cp.async.wait_group %0;" :: "n"(N));
}

// ---------------- math ----------------
// MUFU rsqrt (~2^-22 rel err — MORE accurate than the old 2-step-Newton
// FMA emulation at 4.6e-6). Cost model correction (R11 post-mortem): MUFU
// rt is per WARP-instruction; all 20 rsqrts/matrix = 1.3M MUFU warp-instrs
// = ~10us chip-busy, fully hidden. The FMA emulation burned ~35% of all
// issue slots for nothing.
__device__ __forceinline__ float rsqrt_mufu(float x) {
    float y;
    asm("rsqrt.approx.f32 %0, %1;" : "=f"(y) : "f"(x));
    return y;
}

// EXACT annihilating Givens rotation on plane (p,q), division-free.
// 9 rotations (3 sweeps) is the verified accuracy floor: 6 rotations gave
// rel_err 3.5e-3 (R11 FAIL); 9 give 4.4e-5 (R10 PASS).
template <bool OFFDIAG>
__device__ __forceinline__ void jrot(float& app, float& aqq, float& apq,
                                     float& apr, float& aqr,
                                     float vp[3], float vq[3]) {
    float d  = app - aqq;
    float r2 = fmaf(d, d, 4.0f * apq * apq);
    float w  = rsqrt_mufu(fmaxf(r2, 1e-30f));
    float cos2t = fabsf(d) * w;                      // <= 1 always
    float sin2t = 2.0f * apq * copysignf(w, d);      // <= 1 always
    float u     = fmaf(0.5f, cos2t, 0.5f);           // in [0.5, 1]
    float invc  = rsqrt_mufu(u);
    float c = u * invc;                              // sqrt(u)
    float s = 0.5f * sin2t * invc;
    bool tiny = (r2 < 1e-24f);
    c = tiny ? 1.0f : c;
    s = tiny ? 0.0f : s;

    float half_sum = 0.5f * (app + aqq);
    float t_pp = fmaf(0.5f * d, cos2t, fmaf(apq, sin2t, half_sum));
    float t_qq = fmaf(2.0f, half_sum, -t_pp);        // trace preservation
    app = t_pp; aqq = t_qq; apq = 0.0f;
    if (OFFDIAG) {
        float t_pr = fmaf(c, apr, s * aqr);
        float t_qr = fmaf(c, aqr, -s * apr);
        apr = t_pr; aqr = t_qr;
    }
#pragma unroll
    for (int i = 0; i < 3; i++) {
        float a = vp[i], b = vq[i];
        vp[i] = fmaf(c, a, s * b);
        vq[i] = fmaf(c, b, -s * a);
    }
}

__device__ __forceinline__ void cross3(const float a[3], const float b[3], float o[3]) {
    o[0] = fmaf(a[1], b[2], -a[2] * b[1]);
    o[1] = fmaf(a[2], b[0], -a[0] * b[2]);
    o[2] = fmaf(a[0], b[1], -a[1] * b[0]);
}

// ---------------- kernel ----------------
__global__ void __launch_bounds__(NT, 8)
orientation_bfn_kernel(const float* __restrict__ Rc,
                       const float* __restrict__ tarr,
                       const float* __restrict__ nz,
                       const float* __restrict__ ep,
                       float* __restrict__ out,
                       int ntiles, int tshift, int tiles_per_t) {
    // Single raw staging buffer (13.8 KB) + R staging (4.6 KB) = 18.4 KB.
    __shared__ float4 raw[3][TILE_F4];
    __shared__ float4 rbuf[TILE_F4];

    const int tid = threadIdx.x;

    // Prologue: prefetch first tile.
    int tile0 = blockIdx.x;
    {
        uint32_t sb = smem_u32(&raw[0][0]);
        const float4* r4 = reinterpret_cast<const float4*>(Rc) + (long long)tile0 * TILE_F4;
        const float4* n4 = reinterpret_cast<const float4*>(nz) + (long long)tile0 * TILE_F4;
        const float4* e4 = reinterpret_cast<const float4*>(ep) + (long long)tile0 * TILE_F4;
#pragma unroll
        for (int i = tid; i < TILE_F4; i += NT) {
            cp16(sb + (0 * TILE_F4 + i) * 16, r4 + i);
            cp16(sb + (1 * TILE_F4 + i) * 16, n4 + i);
            cp16(sb + (2 * TILE_F4 + i) * 16, e4 + i);
        }
        cp_commit();
    }

    for (int tile = tile0; tile < ntiles; tile += GRID_BLOCKS) {
        cp_wait<0>();
        __syncthreads();    // raw tile visible to all threads

        const int t_idx = (tshift >= 0) ? (tile >> tshift) : (tile / tiles_per_t);
        const float tval = __ldg(&tarr[t_idx]);
        const float stv  = sqrtf(tval);

        // Drain raw buffer: F = t*R + sqrt(t)*noise + JITTER*eps into regs
        // (stride 9 across banks -> conflict-free).
        const float* rr = reinterpret_cast<const float*>(&raw[0][0]) + tid * 9;
        const float* rn = reinterpret_cast<const float*>(&raw[1][0]) + tid * 9;
        const float* re = reinterpret_cast<const float*>(&raw[2][0]) + tid * 9;
        float F[9];
#pragma unroll
        for (int k = 0; k < 9; k++)
            F[k] = fmaf(tval, rr[k], fmaf(stv, rn[k], JITTER * re[k]));

        __syncthreads();    // all fuse reads done -> raw buffer reusable

        // Issue next tile's prefetch NOW; latency hides under Jacobi below.
        const int nxt_tile = tile + GRID_BLOCKS;
        if (nxt_tile < ntiles) {
            uint32_t sb = smem_u32(&raw[0][0]);
            const float4* r4 = reinterpret_cast<const float4*>(Rc) + (long long)nxt_tile * TILE_F4;
            const float4* n4 = reinterpret_cast<const float4*>(nz) + (long long)nxt_tile * TILE_F4;
            const float4* e4 = reinterpret_cast<const float4*>(ep) + (long long)nxt_tile * TILE_F4;
#pragma unroll
            for (int i = tid; i < TILE_F4; i += NT) {
                cp16(sb + (0 * TILE_F4 + i) * 16, r4 + i);
                cp16(sb + (1 * TILE_F4 + i) * 16, n4 + i);
                cp16(sb + (2 * TILE_F4 + i) * 16, e4 + i);
            }
            cp_commit();
        }

        // A = F^T F
        float a00 = F[0]*F[0] + F[3]*F[3] + F[6]*F[6];
        float a01 = F[0]*F[1] + F[3]*F[4] + F[6]*F[7];
        float a02 = F[0]*F[2] + F[3]*F[5] + F[6]*F[8];
        float a11 = F[1]*F[1] + F[4]*F[4] + F[7]*F[7];
        float a12 = F[1]*F[2] + F[4]*F[5] + F[7]*F[8];
        float a22 = F[2]*F[2] + F[5]*F[5] + F[8]*F[8];

        float V0[3] = {1.f, 0.f, 0.f};
        float V1[3] = {0.f, 1.f, 0.f};
        float V2[3] = {0.f, 0.f, 1.f};

        // 3 exact cyclic sweeps (verified floor); final rotation skips dead
        // off-diagonal updates.
        jrot<true >(a00, a11, a01, a02, a12, V0, V1);
        jrot<true >(a00, a22, a02, a01, a12, V0, V2);
        jrot<true >(a11, a22, a12, a01, a02, V1, V2);
        jrot<true >(a00, a11, a01, a02, a12, V0, V1);
        jrot<true >(a00, a22, a02, a01, a12, V0, V2);
        jrot<true >(a11, a22, a12, a01, a02, V1, V2);
        jrot<true >(a00, a11, a01, a02, a12, V0, V1);
        jrot<true >(a00, a22, a02, a01, a12, V0, V2);
        jrot<false>(a11, a22, a12, a01, a02, V1, V2);

        // Pick eigenvectors of the largest and middle eigenvalues directly.
        bool gt01 = a00 >= a11;
        bool gt02 = a00 >= a22;
        bool gt12 = a11 >= a22;
        bool max0 = gt01 && gt02;
        bool max1 = (!gt01) && gt12;
        float vmax[3], vmid[3], v3[3];
#pragma unroll
        for (int i = 0; i < 3; i++) {
            float innerMax = gt12 ? V1[i] : V2[i];   // largest among {1,2}
            vmax[i] = max0 ? V0[i] : innerMax;
            float mid_if_max1 = gt02 ? V0[i] : V2[i];
            float mid_if_max2 = gt01 ? V0[i] : V1[i];
            vmid[i] = max0 ? innerMax : (max1 ? mid_if_max1 : mid_if_max2);
        }
        cross3(vmax, vmid, v3);   // right-handed third column, det(V)=+1

        // b_i = F v_i, Gram-Schmidt -> U, R = U V^T
        float b1[3], b2[3];
#pragma unroll
        for (int i = 0; i < 3; i++) {
            b1[i] = fmaf(F[3*i+0], vmax[0], fmaf(F[3*i+1], vmax[1], F[3*i+2] * vmax[2]));
            b2[i] = fmaf(F[3*i+0], vmid[0], fmaf(F[3*i+1], vmid[1], F[3*i+2] * vmid[2]));
        }
        float u1[3], u2[3], u3[3];
        float inv1 = rsqrt_mufu(fmaxf(b1[0]*b1[0] + b1[1]*b1[1] + b1[2]*b1[2], 1e-30f));
#pragma unroll
        for (int i = 0; i < 3; i++) u1[i] = b1[i] * inv1;
        float proj = fmaf(u1[0], b2[0], fmaf(u1[1], b2[1], u1[2] * b2[2]));
#pragma unroll
        for (int i = 0; i < 3; i++) b2[i] = fmaf(-proj, u1[i], b2[i]);
        float inv2 = rsqrt_mufu(fmaxf(b2[0]*b2[0] + b2[1]*b2[1] + b2[2]*b2[2], 1e-30f));
#pragma unroll
        for (int i = 0; i < 3; i++) u2[i] = b2[i] * inv2;
        cross3(u1, u2, u3);   // det(U)=+1; smallest-sigma flip implicit

        // R = U V^T into the R staging buffer (own slot, stride 9).
        float* Rp = reinterpret_cast<float*>(&rbuf[0]) + tid * 9;
#pragma unroll
        for (int i = 0; i < 3; i++)
#pragma unroll
            for (int k = 0; k < 3; k++)
                Rp[3*i + k] = fmaf(u1[i], vmax[k], fmaf(u2[i], vmid[k], u3[i] * v3[k]));

        __syncthreads();      // all R written before cross-thread STG reads

        // Coalesced float4 store. (Next iteration's top barrier orders these
        // rbuf reads before anyone rewrites rbuf.)
        float4* o4 = reinterpret_cast<float4*>(out) + (long long)tile * TILE_F4;
#pragma unroll
        for (int i = tid; i < TILE_F4; i += NT) o4[i] = rbuf[i];
    }
}

extern "C" void kernel_launch(void* const* d_in, const int* in_sizes, int n_in,
                              void* d_out, int out_size) {
    const float* Rc = (const float*)d_in[0];   // R_clean  (N*L*9)
    const float* t  = (const float*)d_in[1];   // t        (N)
    const float* nz = (const float*)d_in[2];   // noise    (N*L*9)
    const float* ep = (const float*)d_in[3];   // eps_noise(N*L*9)
    float* out = (float*)d_out;

    const int total = in_sizes[0];
    const int mats = total / 9;
    const int N = in_sizes[1];
    const int Lmats = mats / N;
    const int ntiles = mats / MPB;             // 16384

    const int tiles_per_t = Lmats / MPB;       // 64 for the bench shape
    int tshift = -1;
    if (tiles_per_t > 0 && (tiles_per_t & (tiles_per_t - 1)) == 0) {
        tshift = 0;
        while ((1 << tshift) != tiles_per_t) tshift++;
    }

    int blocks = ntiles < GRID_BLOCKS ? ntiles : GRID_BLOCKS;
    orientation_bfn_kernel<<<blocks, NT>>>(Rc, t, nz, ep, out,
                                           ntiles, tshift, tiles_per_t);
}

// round 13
// speedup vs baseline: 1.5403x; 1.0241x over previous
#include <cuda_runtime.h>
#include <math.h>
#include <stdint.h>

#define NT 128                  // threads per block
#define MPB 128                 // matrices per tile (1 per thread)
#define TILE_FLOATS (MPB * 9)   // 1152 floats per stream per tile
#define TILE_F4 (TILE_FLOATS/4) // 288 float4
#define GRID_BLOCKS 1184        // 8 blocks/SM x 148 SMs (grid; residency 9)
#define JITTER 1e-6f
#define REPS 1e-26f             // degeneracy bias: orthogonality err <= eps/(2*r2) ~ 5e-15

// ---------------- cp.async helpers ----------------
__device__ __forceinline__ uint32_t smem_u32(const void* p) {
    uint32_t a;
    asm("{ .reg .u64 t; cvta.to.shared.u64 t, %1; cvt.u32.u64 %0, t; }"
        : "=r"(a) : "l"(p));
    return a;
}
__device__ __forceinline__ void cp16(uint32_t dst, const void* src) {
    asm volatile("cp.async.cg.shared.global [%0], [%1], 16;"
                 :: "r"(dst), "l"(src));
}
__device__ __forceinline__ void cp_commit() {
    asm volatile("cp.async.commit_group;");
}
template <int N>
__device__ __forceinline__ void cp_wait() {
    asm volatile("cp.async.wait_group %0;" :: "n"(N));
}

// ---------------- math ----------------
// MUFU rsqrt (~2^-22 rel err). MUFU rt is per WARP-instruction: all 20
// rsqrts/matrix = ~10us chip-busy, fully hidden (R12 verified: rel_err
// 8.7e-7 and -5us vs FMA-pipe Newton emulation).
__device__ __forceinline__ float rsqrt_mufu(float x) {
    float y;
    asm("rsqrt.approx.f32 %0, %1;" : "=f"(y) : "f"(x));
    return y;
}

// EXACT annihilating Givens rotation on plane (p,q), division-free.
// 9 rotations (3 sweeps) is the verified accuracy floor: 6 rotations gave
// rel_err 3.5e-3 (R11 FAIL); 9 give <1e-6 (R12 PASS).
// Degenerate planes handled by the REPS bias in r2 (replaces the old
// SETP+SEL guard): c^2+s^2 = 1 - eps/(2*r2) -> orthogonal to fp32 noise
// for any r2 >= 1e-20; data eigen-gaps give r2 >= ~1e-12.
template <bool OFFDIAG>
__device__ __forceinline__ void jrot(float& app, float& aqq, float& apq,
                                     float& apr, float& aqr,
                                     float vp[3], float vq[3]) {
    float d  = app - aqq;
    float r2 = fmaf(d, d, fmaf(4.0f * apq, apq, REPS));
    float w  = rsqrt_mufu(r2);
    float cos2t = fabsf(d) * w;                      // <= 1 always
    float sin2t = 2.0f * apq * copysignf(w, d);      // <= 1 always
    float u     = fmaf(0.5f, cos2t, 0.5f);           // in [0.5, 1]
    float invc  = rsqrt_mufu(u);
    float c = u * invc;                              // sqrt(u)
    float s = 0.5f * sin2t * invc;

    float half_sum = 0.5f * (app + aqq);
    float t_pp = fmaf(0.5f * d, cos2t, fmaf(apq, sin2t, half_sum));
    float t_qq = fmaf(2.0f, half_sum, -t_pp);        // trace preservation
    app = t_pp; aqq = t_qq; apq = 0.0f;
    if (OFFDIAG) {
        float t_pr = fmaf(c, apr, s * aqr);
        float t_qr = fmaf(c, aqr, -s * apr);
        apr = t_pr; aqr = t_qr;
    }
#pragma unroll
    for (int i = 0; i < 3; i++) {
        float a = vp[i], b = vq[i];
        vp[i] = fmaf(c, a, s * b);
        vq[i] = fmaf(c, b, -s * a);
    }
}

__device__ __forceinline__ void cross3(const float a[3], const float b[3], float o[3]) {
    o[0] = fmaf(a[1], b[2], -a[2] * b[1]);
    o[1] = fmaf(a[2], b[0], -a[0] * b[2]);
    o[2] = fmaf(a[0], b[1], -a[1] * b[0]);
}

// ---------------- kernel ----------------
__global__ void __launch_bounds__(NT, 9)   // 56 regs -> 9 blocks/SM = 36 warps
orientation_bfn_kernel(const float* __restrict__ Rc,
                       const float* __restrict__ tarr,
                       const float* __restrict__ nz,
                       const float* __restrict__ ep,
                       float* __restrict__ out,
                       int ntiles, int tshift, int tiles_per_t) {
    // Single raw staging buffer (13.8 KB) + R staging (4.6 KB) = 18.4 KB.
    __shared__ float4 raw[3][TILE_F4];
    __shared__ float4 rbuf[TILE_F4];

    const int tid = threadIdx.x;

    // Prologue: prefetch first tile.
    int tile0 = blockIdx.x;
    {
        uint32_t sb = smem_u32(&raw[0][0]);
        const float4* r4 = reinterpret_cast<const float4*>(Rc) + (long long)tile0 * TILE_F4;
        const float4* n4 = reinterpret_cast<const float4*>(nz) + (long long)tile0 * TILE_F4;
        const float4* e4 = reinterpret_cast<const float4*>(ep) + (long long)tile0 * TILE_F4;
#pragma unroll
        for (int i = tid; i < TILE_F4; i += NT) {
            cp16(sb + (0 * TILE_F4 + i) * 16, r4 + i);
            cp16(sb + (1 * TILE_F4 + i) * 16, n4 + i);
            cp16(sb + (2 * TILE_F4 + i) * 16, e4 + i);
        }
        cp_commit();
    }

    for (int tile = tile0; tile < ntiles; tile += GRID_BLOCKS) {
        cp_wait<0>();
        __syncthreads();    // raw tile visible to all threads

        const int t_idx = (tshift >= 0) ? (tile >> tshift) : (tile / tiles_per_t);
        const float tval = __ldg(&tarr[t_idx]);
        const float stv  = sqrtf(tval);

        // Drain raw buffer: F = t*R + sqrt(t)*noise + JITTER*eps into regs
        // (stride 9 across banks -> conflict-free).
        const float* rr = reinterpret_cast<const float*>(&raw[0][0]) + tid * 9;
        const float* rn = reinterpret_cast<const float*>(&raw[1][0]) + tid * 9;
        const float* re = reinterpret_cast<const float*>(&raw[2][0]) + tid * 9;
        float F[9];
#pragma unroll
        for (int k = 0; k < 9; k++)
            F[k] = fmaf(tval, rr[k], fmaf(stv, rn[k], JITTER * re[k]));

        __syncthreads();    // all fuse reads done -> raw buffer reusable

        // Issue next tile's prefetch NOW; latency hides under Jacobi below.
        const int nxt_tile = tile + GRID_BLOCKS;
        if (nxt_tile < ntiles) {
            uint32_t sb = smem_u32(&raw[0][0]);
            const float4* r4 = reinterpret_cast<const float4*>(Rc) + (long long)nxt_tile * TILE_F4;
            const float4* n4 = reinterpret_cast<const float4*>(nz) + (long long)nxt_tile * TILE_F4;
            const float4* e4 = reinterpret_cast<const float4*>(ep) + (long long)nxt_tile * TILE_F4;
#pragma unroll
            for (int i = tid; i < TILE_F4; i += NT) {
                cp16(sb + (0 * TILE_F4 + i) * 16, r4 + i);
                cp16(sb + (1 * TILE_F4 + i) * 16, n4 + i);
                cp16(sb + (2 * TILE_F4 + i) * 16, e4 + i);
            }
            cp_commit();
        }

        // A = F^T F
        float a00 = F[0]*F[0] + F[3]*F[3] + F[6]*F[6];
        float a01 = F[0]*F[1] + F[3]*F[4] + F[6]*F[7];
        float a02 = F[0]*F[2] + F[3]*F[5] + F[6]*F[8];
        float a11 = F[1]*F[1] + F[4]*F[4] + F[7]*F[7];
        float a12 = F[1]*F[2] + F[4]*F[5] + F[7]*F[8];
        float a22 = F[2]*F[2] + F[5]*F[5] + F[8]*F[8];

        float V0[3] = {1.f, 0.f, 0.f};
        float V1[3] = {0.f, 1.f, 0.f};
        float V2[3] = {0.f, 0.f, 1.f};

        // 3 exact cyclic sweeps (verified floor); final rotation skips dead
        // off-diagonal updates.
        jrot<true >(a00, a11, a01, a02, a12, V0, V1);
        jrot<true >(a00, a22, a02, a01, a12, V0, V2);
        jrot<true >(a11, a22, a12, a01, a02, V1, V2);
        jrot<true >(a00, a11, a01, a02, a12, V0, V1);
        jrot<true >(a00, a22, a02, a01, a12, V0, V2);
        jrot<true >(a11, a22, a12, a01, a02, V1, V2);
        jrot<true >(a00, a11, a01, a02, a12, V0, V1);
        jrot<true >(a00, a22, a02, a01, a12, V0, V2);
        jrot<false>(a11, a22, a12, a01, a02, V1, V2);

        // Pick eigenvectors of the largest and middle eigenvalues directly.
        bool gt01 = a00 >= a11;
        bool gt02 = a00 >= a22;
        bool gt12 = a11 >= a22;
        bool max0 = gt01 && gt02;
        bool max1 = (!gt01) && gt12;
        float vmax[3], vmid[3], v3[3];
#pragma unroll
        for (int i = 0; i < 3; i++) {
            float innerMax = gt12 ? V1[i] : V2[i];   // largest among {1,2}
            vmax[i] = max0 ? V0[i] : innerMax;
            float mid_if_max1 = gt02 ? V0[i] : V2[i];
            float mid_if_max2 = gt01 ? V0[i] : V1[i];
            vmid[i] = max0 ? innerMax : (max1 ? mid_if_max1 : mid_if_max2);
        }
        cross3(vmax, vmid, v3);   // right-handed third column, det(V)=+1

        // b_i = F v_i, Gram-Schmidt -> U, R = U V^T
        float b1[3], b2[3];
#pragma unroll
        for (int i = 0; i < 3; i++) {
            b1[i] = fmaf(F[3*i+0], vmax[0], fmaf(F[3*i+1], vmax[1], F[3*i+2] * vmax[2]));
            b2[i] = fmaf(F[3*i+0], vmid[0], fmaf(F[3*i+1], vmid[1], F[3*i+2] * vmid[2]));
        }
        float u1[3], u2[3], u3[3];
        float inv1 = rsqrt_mufu(b1[0]*b1[0] + b1[1]*b1[1] + b1[2]*b1[2] + REPS);
#pragma unroll
        for (int i = 0; i < 3; i++) u1[i] = b1[i] * inv1;
        float proj = fmaf(u1[0], b2[0], fmaf(u1[1], b2[1], u1[2] * b2[2]));
#pragma unroll
        for (int i = 0; i < 3; i++) b2[i] = fmaf(-proj, u1[i], b2[i]);
        float inv2 = rsqrt_mufu(b2[0]*b2[0] + b2[1]*b2[1] + b2[2]*b2[2] + REPS);
#pragma unroll
        for (int i = 0; i < 3; i++) u2[i] = b2[i] * inv2;
        cross3(u1, u2, u3);   // det(U)=+1; smallest-sigma flip implicit

        // R = U V^T into the R staging buffer (own slot, stride 9).
        float* Rp = reinterpret_cast<float*>(&rbuf[0]) + tid * 9;
#pragma unroll
        for (int i = 0; i < 3; i++)
#pragma unroll
            for (int k = 0; k < 3; k++)
                Rp[3*i + k] = fmaf(u1[i], vmax[k], fmaf(u2[i], vmid[k], u3[i] * v3[k]));

        __syncthreads();      // all R written before cross-thread STG reads

        // Coalesced float4 store. (Next iteration's top barrier orders these
        // rbuf reads before anyone rewrites rbuf.)
        float4* o4 = reinterpret_cast<float4*>(out) + (long long)tile * TILE_F4;
#pragma unroll
        for (int i = tid; i < TILE_F4; i += NT) o4[i] = rbuf[i];
    }
}

extern "C" void kernel_launch(void* const* d_in, const int* in_sizes, int n_in,
                              void* d_out, int out_size) {
    const float* Rc = (const float*)d_in[0];   // R_clean  (N*L*9)
    const float* t  = (const float*)d_in[1];   // t        (N)
    const float* nz = (const float*)d_in[2];   // noise    (N*L*9)
    const float* ep = (const float*)d_in[3];   // eps_noise(N*L*9)
    float* out = (float*)d_out;

    const int total = in_sizes[0];
    const int mats = total / 9;
    const int N = in_sizes[1];
    const int Lmats = mats / N;
    const int ntiles = mats / MPB;             // 16384

    const int tiles_per_t = Lmats / MPB;       // 64 for the bench shape
    int tshift = -1;
    if (tiles_per_t > 0 && (tiles_per_t & (tiles_per_t - 1)) == 0) {
        tshift = 0;
        while ((1 << tshift) != tiles_per_t) tshift++;
    }

    int blocks = ntiles < GRID_BLOCKS ? ntiles : GRID_BLOCKS;
    orientation_bfn_kernel<<<blocks, NT>>>(Rc, t, nz, ep, out,
                                           ntiles, tshift, tiles_per_t);
}

// round 14
// speedup vs baseline: 1.5534x; 1.0085x over previous
#include <cuda_runtime.h>
#include <math.h>
#include <stdint.h>

#define NT 128                  // threads per block
#define MPB 128                 // matrices per tile (1 per thread)
#define TILE_FLOATS (MPB * 9)   // 1152 floats per stream per tile
#define TILE_F4 (TILE_FLOATS/4) // 288 float4
#define GRID_BLOCKS 1332        // 9 blocks/SM x 148 SMs (matches residency 9)
#define JITTER 1e-6f
#define REPS 1e-26f             // degeneracy bias: orthogonality err <= eps/(2*r2)

// ---------------- cp.async helpers ----------------
__device__ __forceinline__ uint32_t smem_u32(const void* p) {
    uint32_t a;
    asm("{ .reg .u64 t; cvta.to.shared.u64 t, %1; cvt.u32.u64 %0, t; }"
        : "=r"(a) : "l"(p));
    return a;
}
__device__ __forceinline__ void cp16(uint32_t dst, const void* src) {
    asm volatile("cp.async.cg.shared.global [%0], [%1], 16;"
                 :: "r"(dst), "l"(src));
}
__device__ __forceinline__ void cp_commit() {
    asm volatile("cp.async.commit_group;");
}
template <int N>
__device__ __forceinline__ void cp_wait() {
    asm volatile("cp.async.wait_group %0;" :: "n"(N));
}
// Streaming store: output is never re-read -> evict-first, keep L2 for inputs.
__device__ __forceinline__ void stcs4(float4* p, float4 v) {
    asm volatile("st.global.cs.v4.f32 [%0], {%1, %2, %3, %4};"
                 :: "l"(p), "f"(v.x), "f"(v.y), "f"(v.z), "f"(v.w));
}

// ---------------- math ----------------
// MUFU rsqrt (~2^-22 rel err). MUFU rt is per WARP-instruction: all 20
// rsqrts/matrix = ~10us chip-busy, fully hidden (R12 verified).
__device__ __forceinline__ float rsqrt_mufu(float x) {
    float y;
    asm("rsqrt.approx.f32 %0, %1;" : "=f"(y) : "f"(x));
    return y;
}

// EXACT annihilating Givens rotation on plane (p,q), division-free.
// 9 rotations (3 sweeps) is the verified accuracy floor: 6 gave 3.5e-3
// (R11 FAIL); 9 give 8.7e-7 (R12/13 PASS). REPS bias handles degenerate
// planes (orthogonality err <= eps/(2*r2), fp32-invisible for data gaps).
template <bool OFFDIAG>
__device__ __forceinline__ void jrot(float& app, float& aqq, float& apq,
                                     float& apr, float& aqr,
                                     float vp[3], float vq[3]) {
    float d  = app - aqq;
    float r2 = fmaf(d, d, fmaf(4.0f * apq, apq, REPS));
    float w  = rsqrt_mufu(r2);
    float cos2t = fabsf(d) * w;                      // <= 1 always
    float sin2t = 2.0f * apq * copysignf(w, d);      // <= 1 always
    float u     = fmaf(0.5f, cos2t, 0.5f);           // in [0.5, 1]
    float invc  = rsqrt_mufu(u);
    float c = u * invc;                              // sqrt(u)
    float s = 0.5f * sin2t * invc;

    float half_sum = 0.5f * (app + aqq);
    float t_pp = fmaf(0.5f * d, cos2t, fmaf(apq, sin2t, half_sum));
    float t_qq = fmaf(2.0f, half_sum, -t_pp);        // trace preservation
    app = t_pp; aqq = t_qq; apq = 0.0f;
    if (OFFDIAG) {
        float t_pr = fmaf(c, apr, s * aqr);
        float t_qr = fmaf(c, aqr, -s * apr);
        apr = t_pr; aqr = t_qr;
    }
#pragma unroll
    for (int i = 0; i < 3; i++) {
        float a = vp[i], b = vq[i];
        vp[i] = fmaf(c, a, s * b);
        vq[i] = fmaf(c, b, -s * a);
    }
}

__device__ __forceinline__ void cross3(const float a[3], const float b[3], float o[3]) {
    o[0] = fmaf(a[1], b[2], -a[2] * b[1]);
    o[1] = fmaf(a[2], b[0], -a[0] * b[2]);
    o[2] = fmaf(a[0], b[1], -a[1] * b[0]);
}

// ---------------- kernel ----------------
__global__ void __launch_bounds__(NT, 9)   // 56 regs -> 9 blocks/SM = 36 warps
orientation_bfn_kernel(const float* __restrict__ Rc,
                       const float* __restrict__ tarr,
                       const float* __restrict__ nz,
                       const float* __restrict__ ep,
                       float* __restrict__ out,
                       int ntiles, int tshift, int tiles_per_t) {
    // Single raw staging buffer (13.8 KB) + R staging (4.6 KB) = 18.4 KB.
    __shared__ float4 raw[3][TILE_F4];
    __shared__ float4 rbuf[TILE_F4];

    const int tid = threadIdx.x;

    // Prologue: prefetch first tile.
    int tile0 = blockIdx.x;
    if (tile0 < ntiles) {
        uint32_t sb = smem_u32(&raw[0][0]);
        const float4* r4 = reinterpret_cast<const float4*>(Rc) + (long long)tile0 * TILE_F4;
        const float4* n4 = reinterpret_cast<const float4*>(nz) + (long long)tile0 * TILE_F4;
        const float4* e4 = reinterpret_cast<const float4*>(ep) + (long long)tile0 * TILE_F4;
#pragma unroll
        for (int i = tid; i < TILE_F4; i += NT) {
            cp16(sb + (0 * TILE_F4 + i) * 16, r4 + i);
            cp16(sb + (1 * TILE_F4 + i) * 16, n4 + i);
            cp16(sb + (2 * TILE_F4 + i) * 16, e4 + i);
        }
        cp_commit();
    }

    for (int tile = tile0; tile < ntiles; tile += GRID_BLOCKS) {
        // t load overlaps the async-copy wait.
        const int t_idx = (tshift >= 0) ? (tile >> tshift) : (tile / tiles_per_t);
        const float tval = __ldg(&tarr[t_idx]);
        const float stv  = sqrtf(tval);

        cp_wait<0>();
        __syncthreads();    // raw tile visible to all threads

        // Drain raw buffer: F = t*R + sqrt(t)*noise + JITTER*eps into regs
        // (stride 9 across banks -> conflict-free).
        const float* rr = reinterpret_cast<const float*>(&raw[0][0]) + tid * 9;
        const float* rn = reinterpret_cast<const float*>(&raw[1][0]) + tid * 9;
        const float* re = reinterpret_cast<const float*>(&raw[2][0]) + tid * 9;
        float F[9];
#pragma unroll
        for (int k = 0; k < 9; k++)
            F[k] = fmaf(tval, rr[k], fmaf(stv, rn[k], JITTER * re[k]));

        __syncthreads();    // all fuse reads done -> raw buffer reusable

        // Issue next tile's prefetch NOW; latency hides under Jacobi below.
        const int nxt_tile = tile + GRID_BLOCKS;
        if (nxt_tile < ntiles) {
            uint32_t sb = smem_u32(&raw[0][0]);
            const float4* r4 = reinterpret_cast<const float4*>(Rc) + (long long)nxt_tile * TILE_F4;
            const float4* n4 = reinterpret_cast<const float4*>(nz) + (long long)nxt_tile * TILE_F4;
            const float4* e4 = reinterpret_cast<const float4*>(ep) + (long long)nxt_tile * TILE_F4;
#pragma unroll
            for (int i = tid; i < TILE_F4; i += NT) {
                cp16(sb + (0 * TILE_F4 + i) * 16, r4 + i);
                cp16(sb + (1 * TILE_F4 + i) * 16, n4 + i);
                cp16(sb + (2 * TILE_F4 + i) * 16, e4 + i);
            }
            cp_commit();
        }

        // A = F^T F
        float a00 = F[0]*F[0] + F[3]*F[3] + F[6]*F[6];
        float a01 = F[0]*F[1] + F[3]*F[4] + F[6]*F[7];
        float a02 = F[0]*F[2] + F[3]*F[5] + F[6]*F[8];
        float a11 = F[1]*F[1] + F[4]*F[4] + F[7]*F[7];
        float a12 = F[1]*F[2] + F[4]*F[5] + F[7]*F[8];
        float a22 = F[2]*F[2] + F[5]*F[5] + F[8]*F[8];

        float V0[3] = {1.f, 0.f, 0.f};
        float V1[3] = {0.f, 1.f, 0.f};
        float V2[3] = {0.f, 0.f, 1.f};

        // 3 exact cyclic sweeps (verified floor); final rotation skips dead
        // off-diagonal updates.
        jrot<true >(a00, a11, a01, a02, a12, V0, V1);
        jrot<true >(a00, a22, a02, a01, a12, V0, V2);
        jrot<true >(a11, a22, a12, a01, a02, V1, V2);
        jrot<true >(a00, a11, a01, a02, a12, V0, V1);
        jrot<true >(a00, a22, a02, a01, a12, V0, V2);
        jrot<true >(a11, a22, a12, a01, a02, V1, V2);
        jrot<true >(a00, a11, a01, a02, a12, V0, V1);
        jrot<true >(a00, a22, a02, a01, a12, V0, V2);
        jrot<false>(a11, a22, a12, a01, a02, V1, V2);

        // Pick eigenvectors of the largest and middle eigenvalues directly.
        bool gt01 = a00 >= a11;
        bool gt02 = a00 >= a22;
        bool gt12 = a11 >= a22;
        bool max0 = gt01 && gt02;
        bool max1 = (!gt01) && gt12;
        float vmax[3], vmid[3], v3[3];
#pragma unroll
        for (int i = 0; i < 3; i++) {
            float innerMax = gt12 ? V1[i] : V2[i];   // largest among {1,2}
            vmax[i] = max0 ? V0[i] : innerMax;
            float mid_if_max1 = gt02 ? V0[i] : V2[i];
            float mid_if_max2 = gt01 ? V0[i] : V1[i];
            vmid[i] = max0 ? innerMax : (max1 ? mid_if_max1 : mid_if_max2);
        }
        cross3(vmax, vmid, v3);   // right-handed third column, det(V)=+1

        // b_i = F v_i, Gram-Schmidt -> U, R = U V^T
        float b1[3], b2[3];
#pragma unroll
        for (int i = 0; i < 3; i++) {
            b1[i] = fmaf(F[3*i+0], vmax[0], fmaf(F[3*i+1], vmax[1], F[3*i+2] * vmax[2]));
            b2[i] = fmaf(F[3*i+0], vmid[0], fmaf(F[3*i+1], vmid[1], F[3*i+2] * vmid[2]));
        }
        float u1[3], u2[3], u3[3];
        float inv1 = rsqrt_mufu(b1[0]*b1[0] + b1[1]*b1[1] + b1[2]*b1[2] + REPS);
#pragma unroll
        for (int i = 0; i < 3; i++) u1[i] = b1[i] * inv1;
        float proj = fmaf(u1[0], b2[0], fmaf(u1[1], b2[1], u1[2] * b2[2]));
#pragma unroll
        for (int i = 0; i < 3; i++) b2[i] = fmaf(-proj, u1[i], b2[i]);
        float inv2 = rsqrt_mufu(b2[0]*b2[0] + b2[1]*b2[1] + b2[2]*b2[2] + REPS);
#pragma unroll
        for (int i = 0; i < 3; i++) u2[i] = b2[i] * inv2;
        cross3(u1, u2, u3);   // det(U)=+1; smallest-sigma flip implicit

        // R = U V^T into the R staging buffer (own slot, stride 9).
        float* Rp = reinterpret_cast<float*>(&rbuf[0]) + tid * 9;
#pragma unroll
        for (int i = 0; i < 3; i++)
#pragma unroll
            for (int k = 0; k < 3; k++)
                Rp[3*i + k] = fmaf(u1[i], vmax[k], fmaf(u2[i], vmid[k], u3[i] * v3[k]));

        __syncthreads();      // all R written before cross-thread STG reads

        // Coalesced streaming store (output never re-read -> evict-first).
        float4* o4 = reinterpret_cast<float4*>(out) + (long long)tile * TILE_F4;
#pragma unroll
        for (int i = tid; i < TILE_F4; i += NT) stcs4(o4 + i, rbuf[i]);
    }
}

extern "C" void kernel_launch(void* const* d_in, const int* in_sizes, int n_in,
                              void* d_out, int out_size) {
    const float* Rc = (const float*)d_in[0];   // R_clean  (N*L*9)
    const float* t  = (const float*)d_in[1];   // t        (N)
    const float* nz = (const float*)d_in[2];   // noise    (N*L*9)
    const float* ep = (const float*)d_in[3];   // eps_noise(N*L*9)
    float* out = (float*)d_out;

    const int total = in_sizes[0];
    const int mats = total / 9;
    const int N = in_sizes[1];
    const int Lmats = mats / N;
    const int ntiles = mats / MPB;             // 16384

    const int tiles_per_t = Lmats / MPB;       // 64 for the bench shape
    int tshift = -1;
    if (tiles_per_t > 0 && (tiles_per_t & (tiles_per_t - 1)) == 0) {
        tshift = 0;
        while ((1 << tshift) != tiles_per_t) tshift++;
    }

    int blocks = ntiles < GRID_BLOCKS ? ntiles : GRID_BLOCKS;
    orientation_bfn_kernel<<<blocks, NT>>>(Rc, t, nz, ep, out,
                                           ntiles, tshift, tiles_per_t);
}